// round 14
// baseline (speedup 1.0000x reference)
#include <cuda_runtime.h>
#include <cuda_bf16.h>
#include <math.h>

typedef unsigned long long ull;

// ---------------- packed f32x2 helpers ----------------
__device__ __forceinline__ ull pack2(float lo, float hi) {
    ull r; asm("mov.b64 %0, {%1, %2};" : "=l"(r) : "f"(lo), "f"(hi)); return r;
}
__device__ __forceinline__ ull bc2(float v) { return pack2(v, v); }
__device__ __forceinline__ void ffma2(ull& d, ull a, ull b) {
    asm("fma.rn.f32x2 %0, %1, %2, %0;" : "+l"(d) : "l"(a), "l"(b));
}
__device__ __forceinline__ float lo32(ull v) { return __uint_as_float((unsigned)v); }
__device__ __forceinline__ float hi32(ull v) { return __uint_as_float((unsigned)(v >> 32)); }

// ---------------- mma.sync / cp.async helpers ----------------
__device__ __forceinline__ unsigned s2u(const void* p) {
    unsigned a; asm("{ .reg .u64 t; cvta.to.shared.u64 t, %1; cvt.u32.u64 %0, t; }" : "=r"(a) : "l"(p));
    return a;
}
__device__ __forceinline__ void ldsm4t(unsigned* r, unsigned addr) {
    asm volatile("ldmatrix.sync.aligned.m8n8.x4.trans.shared.b16 {%0,%1,%2,%3}, [%4];"
                 : "=r"(r[0]), "=r"(r[1]), "=r"(r[2]), "=r"(r[3]) : "r"(addr));
}
__device__ __forceinline__ void mma16816(float* c, const unsigned* a, const unsigned* b) {
    asm volatile(
        "mma.sync.aligned.m16n8k16.row.col.f32.bf16.bf16.f32 "
        "{%0,%1,%2,%3}, {%4,%5,%6,%7}, {%8,%9}, {%0,%1,%2,%3};"
        : "+f"(c[0]), "+f"(c[1]), "+f"(c[2]), "+f"(c[3])
        : "r"(a[0]), "r"(a[1]), "r"(a[2]), "r"(a[3]), "r"(b[0]), "r"(b[1]));
}
__device__ __forceinline__ void cpa16(unsigned saddr, const void* g) {
    asm volatile("cp.async.cg.shared.global [%0], [%1], 16;" :: "r"(saddr), "l"(g));
}
__device__ __forceinline__ void cpa_commit() { asm volatile("cp.async.commit_group;" ::: "memory"); }
__device__ __forceinline__ void cpa_wait0() { asm volatile("cp.async.wait_group 0;" ::: "memory"); }
__device__ __forceinline__ void cpa_wait1() { asm volatile("cp.async.wait_group 1;" ::: "memory"); }

#define BUFB 26624
#define AL_OFF 8704
#define BH_OFF 17408
#define BL_OFF 22016
#define DYN_SMEM (3*26624)
#define NPU 4096
#define KXOFF ((size_t)NPU*1088)

// ---------------- scratch ----------------
#define BATCH 32
__device__ float g_A[BATCH*64*64*64];
__device__ float g_B[BATCH*128*32*32];
__device__ float g_C[BATCH*128*32*32];
__device__ float g_R[BATCH*32*32*32];
__device__ float g_Z[BATCH*64*32*32];
__device__ float g_Q[BATCH*64*32*32];
__device__ int   g_hist[512];
__device__ float g_ssep[256];
// double-buffered shifted-plane staging (ping-pong to avoid producer/consumer races)
__device__ __align__(16) __nv_bfloat16 g_S0h[3*4096*1088];
__device__ __align__(16) __nv_bfloat16 g_S0l[3*4096*1088];
__device__ __align__(16) __nv_bfloat16 g_S1h[3*4096*1088];
__device__ __align__(16) __nv_bfloat16 g_S1l[3*4096*1088];
__device__ __align__(16) __nv_bfloat16 g_Gh[1024*32768];
__device__ __align__(16) __nv_bfloat16 g_Gl[1024*32768];
__device__ __align__(16) __nv_bfloat16 g_Wh[9*128*128];
__device__ __align__(16) __nv_bfloat16 g_Wl[9*128*128];

// scatter one pixel value into the 3 kx-shifted split-bf16 planes
__device__ __forceinline__ void stage_px(__nv_bfloat16* sh, __nv_bfloat16* sl,
                                         int plane, int y, int x, float v)
{
    __nv_bfloat16 h = __float2bfloat16(v);
    __nv_bfloat16 l = __float2bfloat16(v - __bfloat162float(h));
    size_t rowbase = (size_t)plane * 1088 + (size_t)(y + 1) * 32;
#pragma unroll
    for (int kx = 0; kx < 3; kx++) {
        int c = x - kx + 1;
        if ((unsigned)c < 32u) {
            size_t o = (size_t)kx * KXOFF + rowbase + c;
            sh[o] = h; sl[o] = l;
        }
    }
}

__global__ void zero_kernel(int* hist) {
    int t = blockIdx.x * blockDim.x + threadIdx.x;
    if (t < 512) hist[t] = 0;
}

// ---------------- zero the never-written pad cells of one plane buffer ----------------
__global__ void pad_init(__nv_bfloat16* sh, __nv_bfloat16* sl)
{
    int i = blockIdx.x * 256 + threadIdx.x;
    __nv_bfloat16 z = __float2bfloat16(0.f);
    const int nRow = 3*NPU*64;                 // rows 0 and 33, all planes
    if (i < nRow) {
        int plane = i >> 6; int j = i & 63;
        int r = (j & 32) ? 33 : 0; int c = j & 31;
        size_t o = (size_t)plane * 1088 + r*32 + c;
        sh[o] = z; sl[o] = z;
    } else {
        i -= nRow;                             // kx=0 col0 & kx=2 col31, rows 1..32
        if (i < NPU*32*2) {
            int half = i / (NPU*32); int rest = i % (NPU*32);
            int plane = rest >> 5; int rr = (rest & 31) + 1;
            size_t o = half ? ((size_t)(2*NPU + plane)*1088 + rr*32 + 31)
                            : ((size_t)plane*1088 + rr*32 + 0);
            sh[o] = z; sl[o] = z;
        }
    }
}

// ---------------- stage weights (3x3: [tap][ci][oc]) ----------------
__global__ void stage_w_kernel(const float* __restrict__ w, __nv_bfloat16* __restrict__ wh,
                               __nv_bfloat16* __restrict__ wl, int Cin, int Cout)
{
    int n = Cin * Cout * 9;
    for (int i = blockIdx.x*256 + threadIdx.x; i < n; i += gridDim.x*256) {
        int oc = i / (Cin*9); int rr = i % (Cin*9); int ci = rr / 9; int t = rr % 9;
        float v = w[i];
        __nv_bfloat16 h = __float2bfloat16(v);
        __nv_bfloat16 l = __float2bfloat16(v - __bfloat162float(h));
        size_t dst = ((size_t)t * Cin + ci) * Cout + oc;
        wh[dst] = h; wl[dst] = l;
    }
}

// ---------------- dt1 weight stage: [parity][tap][ci][oc] ----------------
__global__ void stage_w_dt1(const float* __restrict__ w, __nv_bfloat16* __restrict__ wh,
                            __nv_bfloat16* __restrict__ wl)
{
    for (int i = blockIdx.x*256 + threadIdx.x; i < 4*4*128*64; i += gridDim.x*256) {
        int oc = i & 63, ci = (i >> 6) & 127, t = (i >> 13) & 3, p = i >> 15;
        int ky = 2*(t >> 1) + (p >> 1);
        int kx = 2*(t & 1) + (p & 1);
        float v = w[((size_t)oc*128 + ci)*16 + ky*4 + kx];
        __nv_bfloat16 h = __float2bfloat16(v);
        __nv_bfloat16 l = __float2bfloat16(v - __bfloat162float(h));
        wh[i] = h; wl[i] = l;
    }
}

// ---------------- generic im2col stage (conv1) ----------------
__global__ void stage_im2col(const float* __restrict__ in, __nv_bfloat16* __restrict__ ah,
                             __nv_bfloat16* __restrict__ al,
                             int Cin, int CinP, int Hin, int Win, int KW,
                             int stride, int pad, int Hout, int Wout, int Mtot)
{
    int k = blockIdx.x;
    int t = k / CinP, ci = k % CinP;
    int ky = t / KW, kx = t % KW;
    int Mimg = Hout * Wout;
    __nv_bfloat16* dh = ah + (size_t)k * Mtot;
    __nv_bfloat16* dl = al + (size_t)k * Mtot;
    int seg = Mtot / gridDim.y;
    int mend = seg * (blockIdx.y + 1);
    for (int m = seg * blockIdx.y + threadIdx.x; m < mend; m += 256) {
        int b = m / Mimg, pos = m % Mimg;
        int y = pos / Wout, x = pos % Wout;
        float v = 0.f;
        if (ci < Cin) {
            int iy = y*stride - pad + ky, ix = x*stride - pad + kx;
            if ((unsigned)iy < (unsigned)Hin && (unsigned)ix < (unsigned)Win)
                v = in[((size_t)(b*Cin + ci)*Hin + iy)*Win + ix];
        }
        __nv_bfloat16 h = __float2bfloat16(v);
        __nv_bfloat16 l = __float2bfloat16(v - __bfloat162float(h));
        dh[m] = h; dl[m] = l;
    }
}

// ---------------- read-once tiled im2col for conv2 ----------------
__global__ void stage_k4s2(const float* __restrict__ in, __nv_bfloat16* __restrict__ gh,
                           __nv_bfloat16* __restrict__ gl, int Mtot)
{
    __shared__ float tile[67][68];
    int bci = blockIdx.x;
    const float* src = in + (size_t)bci * 4096;
    for (int i = threadIdx.x; i < 67*67; i += 256) {
        int r = i / 67, c = i % 67;
        float v = 0.f;
        int iy = r - 1, ix = c - 1;
        if ((unsigned)iy < 64u && (unsigned)ix < 64u) v = src[iy*64 + ix];
        tile[r][c] = v;
    }
    __syncthreads();
    int b = bci >> 6, ci = bci & 63;
    for (int i = threadIdx.x; i < 16*1024; i += 256) {
        int t = i >> 10, pos = i & 1023;
        int y = pos >> 5, x = pos & 31;
        int ky = t >> 2, kx = t & 3;
        float v = tile[2*y + ky][2*x + kx];
        __nv_bfloat16 h = __float2bfloat16(v);
        __nv_bfloat16 l = __float2bfloat16(v - __bfloat162float(h));
        size_t dst = ((size_t)(t*64 + ci)) * Mtot + (size_t)b*1024 + pos;
        gh[dst] = h; gl[dst] = l;
    }
}

// ---------------- generic weight stage: W[k][oc], OIHW source ----------------
__global__ void stage_w_gen(const float* __restrict__ w, __nv_bfloat16* __restrict__ wh,
                            __nv_bfloat16* __restrict__ wl,
                            int Cin, int CinP, int Cout, int T)
{
    int K = T * CinP;
    int ntot = K * Cout;
    for (int i = blockIdx.x*256 + threadIdx.x; i < ntot; i += gridDim.x*256) {
        int k = i / Cout, oc = i % Cout;
        int t = k / CinP, ci = k % CinP;
        float v = (ci < Cin) ? w[((size_t)oc*Cin + ci)*T + t] : 0.f;
        __nv_bfloat16 h = __float2bfloat16(v);
        __nv_bfloat16 l = __float2bfloat16(v - __bfloat162float(h));
        wh[(size_t)k*Cout + oc] = h; wl[(size_t)k*Cout + oc] = l;
    }
}

// ---------------- MMA core macro body ----------------
#define MMA_BODY(aHb, aLb, bHb, bLb)                                              \
    _Pragma("unroll")                                                             \
    for (int kf = 0; kf < 2; kf++) {                                              \
        unsigned Ah[2][4], Al[2][4];                                              \
        int akrow = kf*16 + ((sub & 2) ? 8 : 0) + r;                              \
        int acoff = (sub & 1) ? 8 : 0;                                            \
        _Pragma("unroll")                                                         \
        for (int mf = 0; mf < 2; mf++) {                                          \
            unsigned off = (unsigned)(akrow*272 + (wm*32 + mf*16 + acoff)*2);     \
            ldsm4t(Ah[mf], (aHb) + off);                                          \
            ldsm4t(Al[mf], (aLb) + off);                                          \
        }                                                                         \
        unsigned Bh[4][2], Bl[4][2];                                              \
        int bkrow = kf*16 + ((sub & 1) ? 8 : 0) + r;                              \
        int bcoff = (sub & 2) ? 8 : 0;                                            \
        _Pragma("unroll")                                                         \
        for (int nf2 = 0; nf2 < 4; nf2 += 2) {                                    \
            if (nf2 < nfrags) {                                                   \
                unsigned off = (unsigned)(bkrow*144 + (wn*warpN + nf2*8 + bcoff)*2); \
                unsigned t4[4];                                                   \
                ldsm4t(t4, (bHb) + off);                                          \
                Bh[nf2][0] = t4[0]; Bh[nf2][1] = t4[1];                           \
                Bh[nf2+1][0] = t4[2]; Bh[nf2+1][1] = t4[3];                       \
                ldsm4t(t4, (bLb) + off);                                          \
                Bl[nf2][0] = t4[0]; Bl[nf2][1] = t4[1];                           \
                Bl[nf2+1][0] = t4[2]; Bl[nf2+1][1] = t4[3];                       \
            }                                                                     \
        }                                                                         \
        _Pragma("unroll")                                                         \
        for (int mf = 0; mf < 2; mf++)                                            \
            _Pragma("unroll")                                                     \
            for (int nf = 0; nf < 4; nf++) {                                      \
                if (nf < nfrags) {                                                \
                    mma16816(acc[mf][nf], Ah[mf], Bh[nf]);                        \
                    mma16816(acc[mf][nf], Ah[mf], Bl[nf]);                        \
                    mma16816(acc[mf][nf], Al[mf], Bh[nf]);                        \
                }                                                                 \
            }                                                                     \
    }

// ---------------- generic GEMM, 3-stage pipeline, optional fused staging ----------------
__global__ void __launch_bounds__(256)
gemm_wmma(const __nv_bfloat16* __restrict__ ah, const __nv_bfloat16* __restrict__ al,
          const __nv_bfloat16* __restrict__ wh, const __nv_bfloat16* __restrict__ wl,
          const float* __restrict__ bias, float* __restrict__ out,
          int K, int Cout, int NT, int Mtot, int Mimg, int outRelu,
          __nv_bfloat16* sgh, __nv_bfloat16* sgl)
{
    extern __shared__ char dyn[];
    unsigned sm0 = s2u(dyn);
    int tid = threadIdx.x, lane = tid & 31, warp = tid >> 5;
    int wm = warp >> 1, wn = warp & 1;
    int warpN = NT >> 1, nfrags = warpN >> 3;
    int m0 = blockIdx.x * 128, ocb = blockIdx.y * NT;
    int nb = NT >> 3;
    int nch = K >> 5;
    float acc[2][4][4];
#pragma unroll
    for (int mf = 0; mf < 2; mf++)
#pragma unroll
        for (int nf = 0; nf < 4; nf++)
#pragma unroll
            for (int j = 0; j < 4; j++) acc[mf][nf][j] = 0.f;
    int sub = lane >> 3, r = lane & 7;

    auto LD = [&](int c) {
        int kc = c << 5;
        unsigned base = sm0 + (c % 3) * BUFB;
        for (int i = tid; i < 512; i += 256) {
            int kk = i >> 4, q = i & 15;
            size_t go = (size_t)(kc + kk) * Mtot + m0 + q*8;
            cpa16(base + kk*272 + q*16, ah + go);
            cpa16(base + AL_OFF + kk*272 + q*16, al + go);
        }
        for (int i = tid; i < 32*nb; i += 256) {
            int kk = i / nb, q = i % nb;
            size_t wsrc = (size_t)(kc + kk) * Cout + ocb + q*8;
            cpa16(base + BH_OFF + kk*144 + q*16, wh + wsrc);
            cpa16(base + BL_OFF + kk*144 + q*16, wl + wsrc);
        }
    };

    LD(0); cpa_commit();
    if (nch > 1) { LD(1); cpa_commit(); }
    for (int c = 0; c < nch; c++) {
        if (c + 1 < nch) cpa_wait1(); else cpa_wait0();
        __syncthreads();
        if (c + 2 < nch) { LD(c + 2); cpa_commit(); }
        unsigned aHb = sm0 + (c % 3)*BUFB, aLb = aHb + AL_OFF, bHb = aHb + BH_OFF, bLb = aHb + BL_OFF;
        MMA_BODY(aHb, aLb, bHb, bLb)
        __syncthreads();
    }

    int g = lane >> 2, tig = lane & 3;
    int b = m0 / Mimg;
    int base = m0 - b * Mimg;
    float* ob = out + (size_t)b * Cout * Mimg;
#pragma unroll
    for (int mf = 0; mf < 2; mf++) {
        int p1 = base + wm*32 + mf*16 + g;
        int p2 = p1 + 8;
#pragma unroll
        for (int nf = 0; nf < 4; nf++) {
            if (nf < nfrags) {
                int n0 = ocb + wn*warpN + nf*8 + 2*tig;
                float b0 = bias ? bias[n0] : 0.f;
                float b1 = bias ? bias[n0+1] : 0.f;
                float v00 = acc[mf][nf][0] + b0, v01 = acc[mf][nf][1] + b1;
                float v10 = acc[mf][nf][2] + b0, v11 = acc[mf][nf][3] + b1;
                if (outRelu) {
                    v00 = fmaxf(v00, 0.f); v01 = fmaxf(v01, 0.f);
                    v10 = fmaxf(v10, 0.f); v11 = fmaxf(v11, 0.f);
                }
                ob[(size_t)n0*Mimg + p1]     = v00;
                ob[(size_t)(n0+1)*Mimg + p1] = v01;
                ob[(size_t)n0*Mimg + p2]     = v10;
                ob[(size_t)(n0+1)*Mimg + p2] = v11;
                if (sgh) {
                    int pl0 = b*Cout + n0;
                    stage_px(sgh, sgl, pl0,   p1 >> 5, p1 & 31, v00);
                    stage_px(sgh, sgl, pl0+1, p1 >> 5, p1 & 31, v01);
                    stage_px(sgh, sgl, pl0,   p2 >> 5, p2 & 31, v10);
                    stage_px(sgh, sgl, pl0+1, p2 >> 5, p2 & 31, v11);
                }
            }
        }
    }
}

// ---------------- warp-MMA 3x3 conv, 3-stage pipeline, optional fused staging ----------------
// NOTE: sgh/sgl MUST point to a DIFFERENT plane buffer than sh/sl (ping-pong).
__global__ void __launch_bounds__(256)
conv3x3_wmma(const __nv_bfloat16* __restrict__ sh, const __nv_bfloat16* __restrict__ sl,
             const __nv_bfloat16* __restrict__ wh, const __nv_bfloat16* __restrict__ wl,
             const float* __restrict__ bias, float* __restrict__ out,
             int Cin, int Cout, int NT,
             __nv_bfloat16* sgh, __nv_bfloat16* sgl)
{
    extern __shared__ char dyn[];
    unsigned sm0 = s2u(dyn);
    int tid = threadIdx.x, lane = tid & 31, warp = tid >> 5;
    int wm = warp >> 1, wn = warp & 1;
    int warpN = NT >> 1, nfrags = warpN >> 3;
    int y0 = blockIdx.x * 4, ocb = blockIdx.y * NT, b = blockIdx.z;
    int cpt = Cin >> 5;
    int nch = 9 * cpt;
    int nb = NT >> 3;
    float acc[2][4][4];
#pragma unroll
    for (int mf = 0; mf < 2; mf++)
#pragma unroll
        for (int nf = 0; nf < 4; nf++)
#pragma unroll
            for (int j = 0; j < 4; j++) acc[mf][nf][j] = 0.f;
    int sub = lane >> 3, r = lane & 7;

    auto LD = [&](int c) {
        int tap = c / cpt, cc = c - tap*cpt;
        int ky = tap / 3, kx = tap % 3;
        size_t gbase = (size_t)kx * KXOFF + ((size_t)b * Cin + cc*32) * 1088;
        unsigned base = sm0 + (c % 3) * BUFB;
        for (int i = tid; i < 512; i += 256) {
            int ci = i >> 4, q = i & 15;
            size_t go = gbase + (size_t)ci * 1088 + (size_t)(y0 + ky) * 32 + q*8;
            cpa16(base + ci*272 + q*16, sh + go);
            cpa16(base + AL_OFF + ci*272 + q*16, sl + go);
        }
        for (int i = tid; i < 32*nb; i += 256) {
            int ci = i / nb, q = i % nb;
            size_t wsrc = ((size_t)tap * Cin + cc*32 + ci) * Cout + ocb + q*8;
            cpa16(base + BH_OFF + ci*144 + q*16, wh + wsrc);
            cpa16(base + BL_OFF + ci*144 + q*16, wl + wsrc);
        }
    };

    LD(0); cpa_commit();
    LD(1); cpa_commit();
    for (int c = 0; c < nch; c++) {
        if (c + 1 < nch) cpa_wait1(); else cpa_wait0();
        __syncthreads();
        if (c + 2 < nch) { LD(c + 2); cpa_commit(); }
        unsigned aHb = sm0 + (c % 3)*BUFB, aLb = aHb + AL_OFF, bHb = aHb + BH_OFF, bLb = aHb + BL_OFF;
        MMA_BODY(aHb, aLb, bHb, bLb)
        __syncthreads();
    }

    int g = lane >> 2, tig = lane & 3;
    float* ob = out + (size_t)b * Cout * 1024;
#pragma unroll
    for (int mf = 0; mf < 2; mf++) {
        int m1 = wm*32 + mf*16 + g;
        int m2 = m1 + 8;
        int p1 = (y0 + (m1 >> 5))*32 + (m1 & 31);
        int p2 = (y0 + (m2 >> 5))*32 + (m2 & 31);
#pragma unroll
        for (int nf = 0; nf < 4; nf++) {
            if (nf < nfrags) {
                int n0 = ocb + wn*warpN + nf*8 + 2*tig;
                float b0 = bias ? bias[n0] : 0.f;
                float b1 = bias ? bias[n0+1] : 0.f;
                float v00 = acc[mf][nf][0] + b0, v01 = acc[mf][nf][1] + b1;
                float v10 = acc[mf][nf][2] + b0, v11 = acc[mf][nf][3] + b1;
                ob[(size_t)n0*1024 + p1]     = v00;
                ob[(size_t)(n0+1)*1024 + p1] = v01;
                ob[(size_t)n0*1024 + p2]     = v10;
                ob[(size_t)(n0+1)*1024 + p2] = v11;
                if (sgh) {
                    int pl0 = b*Cout + n0;
                    stage_px(sgh, sgl, pl0,   p1 >> 5, p1 & 31, fmaxf(v00, 0.f));
                    stage_px(sgh, sgl, pl0+1, p1 >> 5, p1 & 31, fmaxf(v01, 0.f));
                    stage_px(sgh, sgl, pl0,   p2 >> 5, p2 & 31, fmaxf(v10, 0.f));
                    stage_px(sgh, sgl, pl0+1, p2 >> 5, p2 & 31, fmaxf(v11, 0.f));
                }
            }
        }
    }
}

// ---------------- dt1 convT via parity GEMMs, 3-stage pipeline ----------------
__global__ void __launch_bounds__(256)
convt_wmma(const __nv_bfloat16* __restrict__ sh, const __nv_bfloat16* __restrict__ sl,
           const __nv_bfloat16* __restrict__ wh, const __nv_bfloat16* __restrict__ wl,
           const float* __restrict__ bias, float* __restrict__ out)
{
    extern __shared__ char dyn[];
    unsigned sm0 = s2u(dyn);
    int tid = threadIdx.x, lane = tid & 31, warp = tid >> 5;
    int wm = warp >> 1, wn = warp & 1;
    const int warpN = 32, nfrags = 4, nb = 8;
    int y0 = blockIdx.x * 4, p = blockIdx.y, b = blockIdx.z;
    int py = p >> 1, px = p & 1;
    const int Cin = 128, nch = 16;
    float acc[2][4][4];
#pragma unroll
    for (int mf = 0; mf < 2; mf++)
#pragma unroll
        for (int nf = 0; nf < 4; nf++)
#pragma unroll
            for (int j = 0; j < 4; j++) acc[mf][nf][j] = 0.f;
    int sub = lane >> 3, r = lane & 7;

    auto LD = [&](int c) {
        int t = c >> 2, cc = c & 3;
        int tyi = t >> 1, txi = t & 1;
        int rowoff = tyi + py;
        int plane = txi + px;
        size_t gbase = (size_t)plane * KXOFF + ((size_t)b * Cin + cc*32) * 1088;
        unsigned base = sm0 + (c % 3) * BUFB;
        for (int i = tid; i < 512; i += 256) {
            int ci = i >> 4, q = i & 15;
            size_t go = gbase + (size_t)ci * 1088 + (size_t)(y0 + rowoff) * 32 + q*8;
            cpa16(base + ci*272 + q*16, sh + go);
            cpa16(base + AL_OFF + ci*272 + q*16, sl + go);
        }
        for (int i = tid; i < 32*nb; i += 256) {
            int ci = i / nb, q = i % nb;
            size_t wsrc = ((size_t)(p*4 + t) * 128 + cc*32 + ci) * 64 + q*8;
            cpa16(base + BH_OFF + ci*144 + q*16, wh + wsrc);
            cpa16(base + BL_OFF + ci*144 + q*16, wl + wsrc);
        }
    };

    LD(0); cpa_commit();
    LD(1); cpa_commit();
    for (int c = 0; c < nch; c++) {
        if (c + 1 < nch) cpa_wait1(); else cpa_wait0();
        __syncthreads();
        if (c + 2 < nch) { LD(c + 2); cpa_commit(); }
        unsigned aHb = sm0 + (c % 3)*BUFB, aLb = aHb + AL_OFF, bHb = aHb + BH_OFF, bLb = aHb + BL_OFF;
        MMA_BODY(aHb, aLb, bHb, bLb)
        __syncthreads();
    }

    int g = lane >> 2, tig = lane & 3;
    float* ob = out + (size_t)b * 64 * 4096;
#pragma unroll
    for (int mf = 0; mf < 2; mf++) {
        int m1 = wm*32 + mf*16 + g;
        int m2 = m1 + 8;
#pragma unroll
        for (int mm = 0; mm < 2; mm++) {
            int m = mm ? m2 : m1;
            int y = y0 + (m >> 5), x = m & 31;
            int opix = (2*y + py)*64 + 2*x + px;
#pragma unroll
            for (int nf = 0; nf < 4; nf++) {
                int n0 = wn*warpN + nf*8 + 2*tig;
                float v0 = acc[mf][nf][mm*2 + 0] + bias[n0];
                float v1 = acc[mf][nf][mm*2 + 1] + bias[n0+1];
                ob[(size_t)n0*4096 + opix]     = fmaxf(v0, 0.f);
                ob[(size_t)(n0+1)*4096 + opix] = fmaxf(v1, 0.f);
            }
        }
    }
}

// ---------------- conv 1x1: relu(in) @ w, +bias, +res, optional fused staging ----------------
__global__ void __launch_bounds__(256, 3)
conv1x1_f2_kernel(const float* __restrict__ in, const float* __restrict__ w,
                  const float* __restrict__ bias, const float* __restrict__ hres,
                  float* __restrict__ out, int Cin, int Cout,
                  __nv_bfloat16* sgh, __nv_bfloat16* sgl)
{
    __shared__ ull s_w[128][16];
    int tid = threadIdx.x;
    int pos = tid & 63, ocg = tid >> 6;
    int s0 = blockIdx.x * 256 + pos * 4;
    int ocb = blockIdx.y * 32;
    int b = blockIdx.z;
    float* swf = (float*)s_w;
    for (int i = tid; i < Cin * 32; i += 256) {
        int ocl = i / Cin; int ci = i % Cin;
        swf[ci*32 + ocl] = w[(ocb + ocl)*Cin + ci];
    }
    __syncthreads();
    ull acc[4][4];
#pragma unroll
    for (int p = 0; p < 4; p++)
#pragma unroll
        for (int j = 0; j < 4; j++) acc[p][j] = 0ull;

    for (int ci = 0; ci < Cin; ci++) {
        float4 iv = *(const float4*)&in[((size_t)(b*Cin + ci) << 10) + s0];
        ull b0 = bc2(fmaxf(iv.x, 0.f)), b1 = bc2(fmaxf(iv.y, 0.f));
        ull b2 = bc2(fmaxf(iv.z, 0.f)), b3 = bc2(fmaxf(iv.w, 0.f));
        ull wr[4];
#pragma unroll
        for (int j = 0; j < 4; j++) wr[j] = s_w[ci][ocg*4 + j];
#pragma unroll
        for (int j = 0; j < 4; j++) {
            ffma2(acc[0][j], b0, wr[j]);
            ffma2(acc[1][j], b1, wr[j]);
            ffma2(acc[2][j], b2, wr[j]);
            ffma2(acc[3][j], b3, wr[j]);
        }
    }
    int y = s0 >> 5, x0 = s0 & 31;
#pragma unroll
    for (int j = 0; j < 4; j++) {
#pragma unroll
        for (int lane = 0; lane < 2; lane++) {
            int oc = ocb + ocg*8 + 2*j + lane;
            size_t base = (((size_t)b*Cout + oc) << 10) + s0;
            float bv = bias ? bias[oc] : 0.f;
            float4 hv = make_float4(0.f, 0.f, 0.f, 0.f);
            if (hres) hv = *(const float4*)&hres[base];
            float4 ov;
            ov.x = (lane ? hi32(acc[0][j]) : lo32(acc[0][j])) + bv + hv.x;
            ov.y = (lane ? hi32(acc[1][j]) : lo32(acc[1][j])) + bv + hv.y;
            ov.z = (lane ? hi32(acc[2][j]) : lo32(acc[2][j])) + bv + hv.z;
            ov.w = (lane ? hi32(acc[3][j]) : lo32(acc[3][j])) + bv + hv.w;
            *(float4*)&out[base] = ov;
            if (sgh) {
                int pl = b*Cout + oc;
                stage_px(sgh, sgl, pl, y, x0,     fmaxf(ov.x, 0.f));
                stage_px(sgh, sgl, pl, y, x0 + 1, fmaxf(ov.y, 0.f));
                stage_px(sgh, sgl, pl, y, x0 + 2, fmaxf(ov.z, 0.f));
                stage_px(sgh, sgl, pl, y, x0 + 3, fmaxf(ov.w, 0.f));
            }
        }
    }
}

// ---------------- vector quantizer, fused Q staging ----------------
__global__ void vq_kernel(const float* __restrict__ z, const float* __restrict__ cb,
                          float* __restrict__ qc, int* __restrict__ hist,
                          float* __restrict__ ssep,
                          __nv_bfloat16* sgh, __nv_bfloat16* sgl)
{
    __shared__ ull s_cb[128][32];
    __shared__ float s_cn[128];
    __shared__ int s_hist[512];
    __shared__ float s_red[128];
    int tid = threadIdx.x;
    for (int i = tid; i < 512; i += 128) s_hist[i] = 0;

    int n = blockIdx.x * 128 + tid;
    int b = n >> 10, s = n & 1023;
    ull zp[32];
    float zv[64];
#pragma unroll
    for (int d = 0; d < 64; d++) zv[d] = z[(((size_t)b * 64 + d) << 10) + s];
#pragma unroll
    for (int j = 0; j < 32; j++) zp[j] = pack2(zv[2*j], zv[2*j+1]);

    const ull* cbu = (const ull*)cb;
    float best = 3.4e38f; int bi = 0;
    for (int k0 = 0; k0 < 512; k0 += 128) {
        __syncthreads();
        for (int i = tid; i < 128*32; i += 128)
            s_cb[i >> 5][i & 31] = cbu[((size_t)k0 << 5) + i];
        __syncthreads();
        {
            float cn = 0.f;
#pragma unroll
            for (int j = 0; j < 32; j++) {
                ull p = s_cb[tid][j];
                float a = lo32(p), bb = hi32(p);
                cn += a*a + bb*bb;
            }
            s_cn[tid] = cn;
        }
        __syncthreads();
        for (int k = 0; k < 128; k++) {
            ull dp = 0ull;
#pragma unroll
            for (int j = 0; j < 32; j++) ffma2(dp, zp[j], s_cb[k][j]);
            float dot = lo32(dp) + hi32(dp);
            float dd = s_cn[k] - 2.f * dot;
            if (dd < best) { best = dd; bi = k0 + k; }
        }
    }
    float sq = 0.f;
    const float* c = cb + ((size_t)bi << 6);
    int y = s >> 5, x = s & 31;
#pragma unroll
    for (int d = 0; d < 64; d++) {
        float cv = c[d];
        qc[(((size_t)b * 64 + d) << 10) + s] = cv;
        stage_px(sgh, sgl, b*64 + d, y, x, cv);
        float df = cv - zv[d];
        sq += df * df;
    }
    atomicAdd(&s_hist[bi], 1);
    s_red[tid] = sq;
    __syncthreads();
    for (int st = 64; st > 0; st >>= 1) {
        if (tid < st) s_red[tid] += s_red[tid + st];
        __syncthreads();
    }
    if (tid == 0) ssep[blockIdx.x] = s_red[0];
    for (int i = tid; i < 512; i += 128)
        if (s_hist[i]) atomicAdd(&hist[i], s_hist[i]);
}

// ---------------- dt2: convT (64->3), 4-oc scalar ----------------
__global__ void convt4s2_kernel(const float* __restrict__ in, const float* __restrict__ w,
                                const float* __restrict__ bias, float* __restrict__ out,
                                int Cin, int Hin, int Win, int Cout, int inRelu, int outRelu)
{
    __shared__ float s_in[8][10][12];
    __shared__ float s_w[4][8][16];
    int tid = threadIdx.x;
    int Hout = Hin * 2, Wout = Win * 2;
    int ntx = Wout >> 4;
    int ox0 = (blockIdx.x % ntx) << 4, oy0 = (blockIdx.x / ntx) << 4;
    int b = blockIdx.z;
    int px = tid & 15, py = tid >> 4;
    int iy0 = oy0 >> 1, ix0 = ox0 >> 1;
    float acc[4];
#pragma unroll
    for (int i = 0; i < 4; i++) acc[i] = 0.f;

    for (int c0 = 0; c0 < Cin; c0 += 8) {
        for (int i = tid; i < 8 * 10 * 10; i += 256) {
            int ci = i / 100; int rr = (i / 10) % 10; int col = i % 10;
            int gy = iy0 - 1 + rr, gx = ix0 - 1 + col;
            float v = 0.f;
            if ((unsigned)gy < (unsigned)Hin && (unsigned)gx < (unsigned)Win)
                v = in[((b*Cin + c0 + ci)*Hin + gy)*Win + gx];
            if (inRelu) v = fmaxf(v, 0.f);
            s_in[ci][rr][col] = v;
        }
        for (int i = tid; i < 4 * 8 * 16; i += 256) {
            int oc = i >> 7; int ci = (i >> 4) & 7; int k = i & 15;
            s_w[oc][ci][k] = (oc < Cout) ? w[((size_t)oc * Cin + c0 + ci)*16 + k] : 0.f;
        }
        __syncthreads();
        int ky0 = py & 1, kx0 = px & 1;
        int r0 = (py + ky0) >> 1;
        int q0 = (px + kx0) >> 1;
#pragma unroll
        for (int ci = 0; ci < 8; ci++) {
            float v00 = s_in[ci][r0][q0];
            float v01 = s_in[ci][r0][q0 + 1];
            float v10 = s_in[ci][r0 + 1][q0];
            float v11 = s_in[ci][r0 + 1][q0 + 1];
#pragma unroll
            for (int oc = 0; oc < 4; oc++) {
                float a = acc[oc];
                a += v00 * s_w[oc][ci][ky0*4 + kx0];
                a += v01 * s_w[oc][ci][ky0*4 + kx0 + 2];
                a += v10 * s_w[oc][ci][(ky0+2)*4 + kx0];
                a += v11 * s_w[oc][ci][(ky0+2)*4 + kx0 + 2];
                acc[oc] = a;
            }
        }
        __syncthreads();
    }
#pragma unroll
    for (int oc = 0; oc < 4; oc++) {
        if (oc < Cout) {
            float r = acc[oc] + bias[oc];
            if (outRelu) r = fmaxf(r, 0.f);
            out[(((size_t)b * Cout + oc)*Hout + oy0 + py)*Wout + ox0 + px] = r;
        }
    }
}

// ---------------- finalize ----------------
__global__ void finalize_kernel(const int* __restrict__ hist, const float* __restrict__ ssep,
                                float* __restrict__ out, int lastIdx)
{
    __shared__ float red[512];
    __shared__ float red2[256];
    int t = threadIdx.x;
    float p = hist[t] * (1.0f / 32768.0f);
    red[t] = p * logf(p + 1e-10f);
    if (t < 256) red2[t] = ssep[t];
    __syncthreads();
    for (int st = 256; st > 0; st >>= 1) {
        if (t < st) red[t] += red[t + st];
        __syncthreads();
    }
    for (int st = 128; st > 0; st >>= 1) {
        if (t < st) red2[t] += red2[t + st];
        __syncthreads();
    }
    if (t == 0) {
        out[0] = red2[0] * 1.25f / (32768.0f * 64.0f);
        out[lastIdx] = expf(-red[0]);
    }
}

// ---------------- launch ----------------
extern "C" void kernel_launch(void* const* d_in, const int* in_sizes, int n_in,
                              void* d_out, int out_size)
{
    const float* x     = (const float*)d_in[0];
    const float* e_w1  = (const float*)d_in[1];
    const float* e_b1  = (const float*)d_in[2];
    const float* e_w2  = (const float*)d_in[3];
    const float* e_b2  = (const float*)d_in[4];
    const float* e_w3  = (const float*)d_in[5];
    const float* e_b3  = (const float*)d_in[6];
    const float* e_r1a = (const float*)d_in[7];
    const float* e_r1b = (const float*)d_in[8];
    const float* e_r2a = (const float*)d_in[9];
    const float* e_r2b = (const float*)d_in[10];
    const float* pre_w = (const float*)d_in[11];
    const float* pre_b = (const float*)d_in[12];
    const float* cb    = (const float*)d_in[13];
    const float* d_w1  = (const float*)d_in[14];
    const float* d_b1  = (const float*)d_in[15];
    const float* d_r1a = (const float*)d_in[16];
    const float* d_r1b = (const float*)d_in[17];
    const float* d_r2a = (const float*)d_in[18];
    const float* d_r2b = (const float*)d_in[19];
    const float* dt_w1 = (const float*)d_in[20];
    const float* dt_b1 = (const float*)d_in[21];
    const float* dt_w2 = (const float*)d_in[22];
    const float* dt_b2 = (const float*)d_in[23];
    float* out = (float*)d_out;

    float *A, *Bb, *C, *R, *Z, *Q, *ssep; int* hist;
    __nv_bfloat16 *S0h, *S0l, *S1h, *S1l, *Gh, *Gl, *Wh, *Wl;
    cudaGetSymbolAddress((void**)&A,    g_A);
    cudaGetSymbolAddress((void**)&Bb,   g_B);
    cudaGetSymbolAddress((void**)&C,    g_C);
    cudaGetSymbolAddress((void**)&R,    g_R);
    cudaGetSymbolAddress((void**)&Z,    g_Z);
    cudaGetSymbolAddress((void**)&Q,    g_Q);
    cudaGetSymbolAddress((void**)&ssep, g_ssep);
    cudaGetSymbolAddress((void**)&hist, g_hist);
    cudaGetSymbolAddress((void**)&S0h,  g_S0h);
    cudaGetSymbolAddress((void**)&S0l,  g_S0l);
    cudaGetSymbolAddress((void**)&S1h,  g_S1h);
    cudaGetSymbolAddress((void**)&S1l,  g_S1l);
    cudaGetSymbolAddress((void**)&Gh,   g_Gh);
    cudaGetSymbolAddress((void**)&Gl,   g_Gl);
    cudaGetSymbolAddress((void**)&Wh,   g_Wh);
    cudaGetSymbolAddress((void**)&Wl,   g_Wl);

    static int smem_set = 0;
    if (!smem_set) {
        cudaFuncSetAttribute(gemm_wmma, cudaFuncAttributeMaxDynamicSharedMemorySize, DYN_SMEM);
        cudaFuncSetAttribute(conv3x3_wmma, cudaFuncAttributeMaxDynamicSharedMemorySize, DYN_SMEM);
        cudaFuncSetAttribute(convt_wmma, cudaFuncAttributeMaxDynamicSharedMemorySize, DYN_SMEM);
        smem_set = 1;
    }

    zero_kernel<<<2, 256>>>(hist);
    pad_init<<<4096, 256>>>(S0h, S0l);
    pad_init<<<4096, 256>>>(S1h, S1l);

    // ---- encoder ----
    stage_w_gen<<<16, 256>>>(e_w1, Wh, Wl, 3, 4, 64, 16);
    stage_im2col<<<dim3(64, 8), 256>>>(x, Gh, Gl, 3, 4, 128, 128, 4, 2, 1, 64, 64, BATCH*4096);
    gemm_wmma<<<dim3(1024, 1), 256, DYN_SMEM>>>(Gh, Gl, Wh, Wl, e_b1, A, 64, 64, 64, BATCH*4096, 4096, 1, nullptr, nullptr);
    stage_w_gen<<<128, 256>>>(e_w2, Wh, Wl, 64, 64, 128, 16);
    stage_k4s2<<<2048, 256>>>(A, Gh, Gl, BATCH*1024);
    // conv2 out Bb; stage (relu'd) -> S0 for e3
    gemm_wmma<<<dim3(256, 2), 256, DYN_SMEM>>>(Gh, Gl, Wh, Wl, e_b2, Bb, 1024, 128, 64, BATCH*1024, 1024, 1, S0h, S0l);

    stage_w_kernel<<<64, 256>>>(e_w3, Wh, Wl, 128, 128);
    // e3 reads S0 -> C; stage relu(C) -> S1 for res1 3x3
    conv3x3_wmma<<<dim3(8, 2, BATCH), 256, DYN_SMEM>>>(S0h, S0l, Wh, Wl, e_b3, C, 128, 128, 64, S1h, S1l);
    stage_w_kernel<<<64, 256>>>(e_r1a, Wh, Wl, 128, 32);
    conv3x3_wmma<<<dim3(8, 1, BATCH), 256, DYN_SMEM>>>(S1h, S1l, Wh, Wl, nullptr, R, 128, 32, 32, nullptr, nullptr);
    // res1 1x1 -> C; stage relu(C) -> S0 for res2 3x3
    conv1x1_f2_kernel<<<dim3(4, 4, BATCH), 256>>>(R, e_r1b, nullptr, C, C, 32, 128, S0h, S0l);
    stage_w_kernel<<<64, 256>>>(e_r2a, Wh, Wl, 128, 32);
    conv3x3_wmma<<<dim3(8, 1, BATCH), 256, DYN_SMEM>>>(S0h, S0l, Wh, Wl, nullptr, R, 128, 32, 32, nullptr, nullptr);
    conv1x1_f2_kernel<<<dim3(4, 4, BATCH), 256>>>(R, e_r2b, nullptr, C, C, 32, 128, nullptr, nullptr);
    conv1x1_f2_kernel<<<dim3(4, 2, BATCH), 256>>>(C, pre_w, pre_b, nullptr, Z, 128, 64, nullptr, nullptr);

    // ---- VQ (stages Q planes -> S1 for d_w1) ----
    vq_kernel<<<256, 128>>>(Z, cb, Q, hist, ssep, S1h, S1l);

    // ---- decoder ----
    stage_w_kernel<<<64, 256>>>(d_w1, Wh, Wl, 64, 128);
    // d_w1 reads S1 -> Bb; stage relu -> S0 for d_r1a
    conv3x3_wmma<<<dim3(8, 2, BATCH), 256, DYN_SMEM>>>(S1h, S1l, Wh, Wl, d_b1, Bb, 64, 128, 64, S0h, S0l);
    stage_w_kernel<<<64, 256>>>(d_r1a, Wh, Wl, 128, 32);
    conv3x3_wmma<<<dim3(8, 1, BATCH), 256, DYN_SMEM>>>(S0h, S0l, Wh, Wl, nullptr, R, 128, 32, 32, nullptr, nullptr);
    // d_r1 1x1 -> Bb; stage relu -> S1 for d_r2a
    conv1x1_f2_kernel<<<dim3(4, 4, BATCH), 256>>>(R, d_r1b, nullptr, Bb, Bb, 32, 128, S1h, S1l);
    stage_w_kernel<<<64, 256>>>(d_r2a, Wh, Wl, 128, 32);
    conv3x3_wmma<<<dim3(8, 1, BATCH), 256, DYN_SMEM>>>(S1h, S1l, Wh, Wl, nullptr, R, 128, 32, 32, nullptr, nullptr);
    // d_r2 1x1 -> Bb; stage relu -> S0 for dt1
    conv1x1_f2_kernel<<<dim3(4, 4, BATCH), 256>>>(R, d_r2b, nullptr, Bb, Bb, 32, 128, S0h, S0l);

    // dt1: convT 128->64 via parity GEMMs (reads S0)
    stage_w_dt1<<<128, 256>>>(dt_w1, Wh, Wl);
    convt_wmma<<<dim3(8, 4, BATCH), 256, DYN_SMEM>>>(S0h, S0l, Wh, Wl, dt_b1, A);

    convt4s2_kernel<<<dim3(64, 1, BATCH), 256>>>(A, dt_w2, dt_b2, out + 1, 64, 64, 64, 3, 0, 0);

    finalize_kernel<<<1, 512>>>(hist, ssep, out, out_size - 1);
}

// round 15
// speedup vs baseline: 1.1153x; 1.1153x over previous
#include <cuda_runtime.h>
#include <cuda_bf16.h>
#include <math.h>

typedef unsigned long long ull;

// ---------------- packed f32x2 helpers ----------------
__device__ __forceinline__ ull pack2(float lo, float hi) {
    ull r; asm("mov.b64 %0, {%1, %2};" : "=l"(r) : "f"(lo), "f"(hi)); return r;
}
__device__ __forceinline__ ull bc2(float v) { return pack2(v, v); }
__device__ __forceinline__ void ffma2(ull& d, ull a, ull b) {
    asm("fma.rn.f32x2 %0, %1, %2, %0;" : "+l"(d) : "l"(a), "l"(b));
}
__device__ __forceinline__ float lo32(ull v) { return __uint_as_float((unsigned)v); }
__device__ __forceinline__ float hi32(ull v) { return __uint_as_float((unsigned)(v >> 32)); }

// ---------------- mma.sync / cp.async helpers ----------------
__device__ __forceinline__ unsigned s2u(const void* p) {
    unsigned a; asm("{ .reg .u64 t; cvta.to.shared.u64 t, %1; cvt.u32.u64 %0, t; }" : "=r"(a) : "l"(p));
    return a;
}
__device__ __forceinline__ void ldsm4t(unsigned* r, unsigned addr) {
    asm volatile("ldmatrix.sync.aligned.m8n8.x4.trans.shared.b16 {%0,%1,%2,%3}, [%4];"
                 : "=r"(r[0]), "=r"(r[1]), "=r"(r[2]), "=r"(r[3]) : "r"(addr));
}
__device__ __forceinline__ void mma16816(float* c, const unsigned* a, const unsigned* b) {
    asm volatile(
        "mma.sync.aligned.m16n8k16.row.col.f32.bf16.bf16.f32 "
        "{%0,%1,%2,%3}, {%4,%5,%6,%7}, {%8,%9}, {%0,%1,%2,%3};"
        : "+f"(c[0]), "+f"(c[1]), "+f"(c[2]), "+f"(c[3])
        : "r"(a[0]), "r"(a[1]), "r"(a[2]), "r"(a[3]), "r"(b[0]), "r"(b[1]));
}
__device__ __forceinline__ void cpa16(unsigned saddr, const void* g) {
    asm volatile("cp.async.cg.shared.global [%0], [%1], 16;" :: "r"(saddr), "l"(g));
}
__device__ __forceinline__ void cpa_commit() { asm volatile("cp.async.commit_group;" ::: "memory"); }
__device__ __forceinline__ void cpa_wait0() { asm volatile("cp.async.wait_group 0;" ::: "memory"); }
__device__ __forceinline__ void cpa_wait1() { asm volatile("cp.async.wait_group 1;" ::: "memory"); }

#define BUFB 26624
#define AL_OFF 8704
#define BH_OFF 17408
#define BL_OFF 22016
#define DYN_SMEM (3*26624)
#define NPU 4096
#define KXOFF ((size_t)NPU*1088)

// ---------------- scratch ----------------
#define BATCH 32
__device__ float g_A[BATCH*64*64*64];
__device__ float g_B[BATCH*128*32*32];
__device__ float g_C[BATCH*128*32*32];
__device__ float g_R[BATCH*32*32*32];
__device__ float g_Z[BATCH*64*32*32];
__device__ int   g_hist[512];
__device__ float g_ssep[256];
__device__ __align__(16) __nv_bfloat16 g_Sh[3*4096*1088];
__device__ __align__(16) __nv_bfloat16 g_Sl[3*4096*1088];
__device__ __align__(16) __nv_bfloat16 g_Gh[1024*32768];
__device__ __align__(16) __nv_bfloat16 g_Gl[1024*32768];
// per-layer staged weights
__device__ __align__(16) __nv_bfloat16 g_W1h[64*64],      g_W1l[64*64];       // conv1
__device__ __align__(16) __nv_bfloat16 g_W2h[1024*128],   g_W2l[1024*128];    // conv2
__device__ __align__(16) __nv_bfloat16 g_W3h[9*128*128],  g_W3l[9*128*128];   // e_w3
__device__ __align__(16) __nv_bfloat16 g_W4h[9*128*32],   g_W4l[9*128*32];    // e_r1a
__device__ __align__(16) __nv_bfloat16 g_W5h[9*128*32],   g_W5l[9*128*32];    // e_r2a
__device__ __align__(16) __nv_bfloat16 g_W6h[9*64*128],   g_W6l[9*64*128];    // d_w1
__device__ __align__(16) __nv_bfloat16 g_W7h[9*128*32],   g_W7l[9*128*32];    // d_r1a
__device__ __align__(16) __nv_bfloat16 g_W8h[9*128*32],   g_W8l[9*128*32];    // d_r2a
__device__ __align__(16) __nv_bfloat16 g_W9h[16*128*64],  g_W9l[16*128*64];   // dt1

__global__ void zero_kernel(int* hist) {
    int t = blockIdx.x * blockDim.x + threadIdx.x;
    if (t < 512) hist[t] = 0;
}

// scatter one pixel into the 3 kx-shifted split-bf16 planes (interior only)
__device__ __forceinline__ void stage_px(__nv_bfloat16* sh, __nv_bfloat16* sl,
                                         int plane, int y, int x, float v)
{
    __nv_bfloat16 h = __float2bfloat16(v);
    __nv_bfloat16 l = __float2bfloat16(v - __bfloat162float(h));
    size_t rowbase = (size_t)plane * 1088 + (size_t)(y + 1) * 32;
#pragma unroll
    for (int kx = 0; kx < 3; kx++) {
        int c = x - kx + 1;
        if ((unsigned)c < 32u) {
            size_t o = (size_t)kx * KXOFF + rowbase + c;
            sh[o] = h; sl[o] = l;
        }
    }
}

// ---------------- stage input (shifted planes) ----------------
__global__ void stage_in_kernel(const float* __restrict__ in, __nv_bfloat16* __restrict__ sh,
                                __nv_bfloat16* __restrict__ sl, int NP, int doRelu)
{
    int plane = blockIdx.x;
    const float* src = in + (size_t)plane * 1024;
    for (int i = threadIdx.x; i < 3*1088; i += 256) {
        int kx = i / 1088; int r = (i % 1088) / 32; int c = i & 31;
        float v = 0.f;
        int sy = r - 1, sx = c + kx - 1;
        if ((unsigned)sy < 32u && (unsigned)sx < 32u) v = src[sy*32 + sx];
        if (doRelu) v = fmaxf(v, 0.f);
        __nv_bfloat16 h = __float2bfloat16(v);
        __nv_bfloat16 l = __float2bfloat16(v - __bfloat162float(h));
        size_t o = ((size_t)kx * NP + plane) * 1088 + r*32 + c;
        sh[o] = h; sl[o] = l;
    }
}

// ---------------- weight-staging device helpers ----------------
__device__ void dev_w33(const float* w, __nv_bfloat16* wh, __nv_bfloat16* wl,
                        int Cin, int Cout, int i0, int stride)
{
    int n = Cin * Cout * 9;
    for (int i = i0; i < n; i += stride) {
        int oc = i / (Cin*9); int rr = i % (Cin*9); int ci = rr / 9; int t = rr % 9;
        float v = w[i];
        __nv_bfloat16 h = __float2bfloat16(v);
        __nv_bfloat16 l = __float2bfloat16(v - __bfloat162float(h));
        size_t dst = ((size_t)t * Cin + ci) * Cout + oc;
        wh[dst] = h; wl[dst] = l;
    }
}
__device__ void dev_w_gen(const float* w, __nv_bfloat16* wh, __nv_bfloat16* wl,
                          int Cin, int CinP, int Cout, int T, int i0, int stride)
{
    int ntot = T * CinP * Cout;
    for (int i = i0; i < ntot; i += stride) {
        int k = i / Cout, oc = i % Cout;
        int t = k / CinP, ci = k % CinP;
        float v = (ci < Cin) ? w[((size_t)oc*Cin + ci)*T + t] : 0.f;
        __nv_bfloat16 h = __float2bfloat16(v);
        __nv_bfloat16 l = __float2bfloat16(v - __bfloat162float(h));
        wh[(size_t)k*Cout + oc] = h; wl[(size_t)k*Cout + oc] = l;
    }
}
__device__ void dev_w_dt1(const float* w, __nv_bfloat16* wh, __nv_bfloat16* wl,
                          int i0, int stride)
{
    for (int i = i0; i < 4*4*128*64; i += stride) {
        int oc = i & 63, ci = (i >> 6) & 127, t = (i >> 13) & 3, p = i >> 15;
        int ky = 2*(t >> 1) + (p >> 1);
        int kx = 2*(t & 1) + (p & 1);
        float v = w[((size_t)oc*128 + ci)*16 + ky*4 + kx];
        __nv_bfloat16 h = __float2bfloat16(v);
        __nv_bfloat16 l = __float2bfloat16(v - __bfloat162float(h));
        wh[i] = h; wl[i] = l;
    }
}

// ---------------- one launch stages ALL weights ----------------
__global__ void stage_all_w(const float* e_w1, const float* e_w2, const float* e_w3,
                            const float* e_r1a, const float* e_r2a, const float* d_w1,
                            const float* d_r1a, const float* d_r2a, const float* dt_w1)
{
    int i0 = blockIdx.x * 256 + threadIdx.x;
    int stride = gridDim.x * 256;
    switch (blockIdx.y) {
    case 0: dev_w_gen(e_w1, g_W1h, g_W1l, 3, 4, 64, 16, i0, stride); break;
    case 1: dev_w_gen(e_w2, g_W2h, g_W2l, 64, 64, 128, 16, i0, stride); break;
    case 2: dev_w33(e_w3,  g_W3h, g_W3l, 128, 128, i0, stride); break;
    case 3: dev_w33(e_r1a, g_W4h, g_W4l, 128, 32, i0, stride); break;
    case 4: dev_w33(e_r2a, g_W5h, g_W5l, 128, 32, i0, stride); break;
    case 5: dev_w33(d_w1,  g_W6h, g_W6l, 64, 128, i0, stride); break;
    case 6: dev_w33(d_r1a, g_W7h, g_W7l, 128, 32, i0, stride); break;
    case 7: dev_w33(d_r2a, g_W8h, g_W8l, 128, 32, i0, stride); break;
    case 8: dev_w_dt1(dt_w1, g_W9h, g_W9l, i0, stride); break;
    }
}

// ---------------- generic im2col stage (conv1) ----------------
__global__ void stage_im2col(const float* __restrict__ in, __nv_bfloat16* __restrict__ ah,
                             __nv_bfloat16* __restrict__ al,
                             int Cin, int CinP, int Hin, int Win, int KW,
                             int stride, int pad, int Hout, int Wout, int Mtot)
{
    int k = blockIdx.x;
    int t = k / CinP, ci = k % CinP;
    int ky = t / KW, kx = t % KW;
    int Mimg = Hout * Wout;
    __nv_bfloat16* dh = ah + (size_t)k * Mtot;
    __nv_bfloat16* dl = al + (size_t)k * Mtot;
    int seg = Mtot / gridDim.y;
    int mend = seg * (blockIdx.y + 1);
    for (int m = seg * blockIdx.y + threadIdx.x; m < mend; m += 256) {
        int b = m / Mimg, pos = m % Mimg;
        int y = pos / Wout, x = pos % Wout;
        float v = 0.f;
        if (ci < Cin) {
            int iy = y*stride - pad + ky, ix = x*stride - pad + kx;
            if ((unsigned)iy < (unsigned)Hin && (unsigned)ix < (unsigned)Win)
                v = in[((size_t)(b*Cin + ci)*Hin + iy)*Win + ix];
        }
        __nv_bfloat16 h = __float2bfloat16(v);
        __nv_bfloat16 l = __float2bfloat16(v - __bfloat162float(h));
        dh[m] = h; dl[m] = l;
    }
}

// ---------------- read-once tiled im2col for conv2 ----------------
__global__ void stage_k4s2(const float* __restrict__ in, __nv_bfloat16* __restrict__ gh,
                           __nv_bfloat16* __restrict__ gl, int Mtot)
{
    __shared__ float tile[67][68];
    int bci = blockIdx.x;
    const float* src = in + (size_t)bci * 4096;
    for (int i = threadIdx.x; i < 67*67; i += 256) {
        int r = i / 67, c = i % 67;
        float v = 0.f;
        int iy = r - 1, ix = c - 1;
        if ((unsigned)iy < 64u && (unsigned)ix < 64u) v = src[iy*64 + ix];
        tile[r][c] = v;
    }
    __syncthreads();
    int b = bci >> 6, ci = bci & 63;
    for (int i = threadIdx.x; i < 16*1024; i += 256) {
        int t = i >> 10, pos = i & 1023;
        int y = pos >> 5, x = pos & 31;
        int ky = t >> 2, kx = t & 3;
        float v = tile[2*y + ky][2*x + kx];
        __nv_bfloat16 h = __float2bfloat16(v);
        __nv_bfloat16 l = __float2bfloat16(v - __bfloat162float(h));
        size_t dst = ((size_t)(t*64 + ci)) * Mtot + (size_t)b*1024 + pos;
        gh[dst] = h; gl[dst] = l;
    }
}

// ---------------- MMA core macro body ----------------
#define MMA_BODY(aHb, aLb, bHb, bLb)                                              \
    _Pragma("unroll")                                                             \
    for (int kf = 0; kf < 2; kf++) {                                              \
        unsigned Ah[2][4], Al[2][4];                                              \
        int akrow = kf*16 + ((sub & 2) ? 8 : 0) + r;                              \
        int acoff = (sub & 1) ? 8 : 0;                                            \
        _Pragma("unroll")                                                         \
        for (int mf = 0; mf < 2; mf++) {                                          \
            unsigned off = (unsigned)(akrow*272 + (wm*32 + mf*16 + acoff)*2);     \
            ldsm4t(Ah[mf], (aHb) + off);                                          \
            ldsm4t(Al[mf], (aLb) + off);                                          \
        }                                                                         \
        unsigned Bh[4][2], Bl[4][2];                                              \
        int bkrow = kf*16 + ((sub & 1) ? 8 : 0) + r;                              \
        int bcoff = (sub & 2) ? 8 : 0;                                            \
        _Pragma("unroll")                                                         \
        for (int nf2 = 0; nf2 < 4; nf2 += 2) {                                    \
            if (nf2 < nfrags) {                                                   \
                unsigned off = (unsigned)(bkrow*144 + (wn*warpN + nf2*8 + bcoff)*2); \
                unsigned t4[4];                                                   \
                ldsm4t(t4, (bHb) + off);                                          \
                Bh[nf2][0] = t4[0]; Bh[nf2][1] = t4[1];                           \
                Bh[nf2+1][0] = t4[2]; Bh[nf2+1][1] = t4[3];                       \
                ldsm4t(t4, (bLb) + off);                                          \
                Bl[nf2][0] = t4[0]; Bl[nf2][1] = t4[1];                           \
                Bl[nf2+1][0] = t4[2]; Bl[nf2+1][1] = t4[3];                       \
            }                                                                     \
        }                                                                         \
        _Pragma("unroll")                                                         \
        for (int mf = 0; mf < 2; mf++)                                            \
            _Pragma("unroll")                                                     \
            for (int nf = 0; nf < 4; nf++) {                                      \
                if (nf < nfrags) {                                                \
                    mma16816(acc[mf][nf], Ah[mf], Bh[nf]);                        \
                    mma16816(acc[mf][nf], Ah[mf], Bl[nf]);                        \
                    mma16816(acc[mf][nf], Al[mf], Bh[nf]);                        \
                }                                                                 \
            }                                                                     \
    }

// ---------------- generic GEMM, 3-stage pipeline ----------------
__global__ void __launch_bounds__(256)
gemm_wmma(const __nv_bfloat16* __restrict__ ah, const __nv_bfloat16* __restrict__ al,
          const __nv_bfloat16* __restrict__ wh, const __nv_bfloat16* __restrict__ wl,
          const float* __restrict__ bias, float* __restrict__ out,
          int K, int Cout, int NT, int Mtot, int Mimg, int outRelu)
{
    extern __shared__ char dyn[];
    unsigned sm0 = s2u(dyn);
    int tid = threadIdx.x, lane = tid & 31, warp = tid >> 5;
    int wm = warp >> 1, wn = warp & 1;
    int warpN = NT >> 1, nfrags = warpN >> 3;
    int m0 = blockIdx.x * 128, ocb = blockIdx.y * NT;
    int nb = NT >> 3;
    int nch = K >> 5;
    float acc[2][4][4];
#pragma unroll
    for (int mf = 0; mf < 2; mf++)
#pragma unroll
        for (int nf = 0; nf < 4; nf++)
#pragma unroll
            for (int j = 0; j < 4; j++) acc[mf][nf][j] = 0.f;
    int sub = lane >> 3, r = lane & 7;

    auto LD = [&](int c) {
        int kc = c << 5;
        unsigned base = sm0 + (c % 3) * BUFB;
        for (int i = tid; i < 512; i += 256) {
            int kk = i >> 4, q = i & 15;
            size_t go = (size_t)(kc + kk) * Mtot + m0 + q*8;
            cpa16(base + kk*272 + q*16, ah + go);
            cpa16(base + AL_OFF + kk*272 + q*16, al + go);
        }
        for (int i = tid; i < 32*nb; i += 256) {
            int kk = i / nb, q = i % nb;
            size_t wsrc = (size_t)(kc + kk) * Cout + ocb + q*8;
            cpa16(base + BH_OFF + kk*144 + q*16, wh + wsrc);
            cpa16(base + BL_OFF + kk*144 + q*16, wl + wsrc);
        }
    };

    LD(0); cpa_commit();
    if (nch > 1) { LD(1); cpa_commit(); }
    for (int c = 0; c < nch; c++) {
        if (c + 1 < nch) cpa_wait1(); else cpa_wait0();
        __syncthreads();
        if (c + 2 < nch) { LD(c + 2); cpa_commit(); }
        unsigned aHb = sm0 + (c % 3)*BUFB, aLb = aHb + AL_OFF, bHb = aHb + BH_OFF, bLb = aHb + BL_OFF;
        MMA_BODY(aHb, aLb, bHb, bLb)
        __syncthreads();
    }

    int g = lane >> 2, tig = lane & 3;
    int b = m0 / Mimg;
    int base = m0 - b * Mimg;
    float* ob = out + (size_t)b * Cout * Mimg;
#pragma unroll
    for (int mf = 0; mf < 2; mf++) {
        int p1 = base + wm*32 + mf*16 + g;
        int p2 = p1 + 8;
#pragma unroll
        for (int nf = 0; nf < 4; nf++) {
            if (nf < nfrags) {
                int n0 = ocb + wn*warpN + nf*8 + 2*tig;
                float b0 = bias ? bias[n0] : 0.f;
                float b1 = bias ? bias[n0+1] : 0.f;
                float v00 = acc[mf][nf][0] + b0, v01 = acc[mf][nf][1] + b1;
                float v10 = acc[mf][nf][2] + b0, v11 = acc[mf][nf][3] + b1;
                if (outRelu) {
                    v00 = fmaxf(v00, 0.f); v01 = fmaxf(v01, 0.f);
                    v10 = fmaxf(v10, 0.f); v11 = fmaxf(v11, 0.f);
                }
                ob[(size_t)n0*Mimg + p1]     = v00;
                ob[(size_t)(n0+1)*Mimg + p1] = v01;
                ob[(size_t)n0*Mimg + p2]     = v10;
                ob[(size_t)(n0+1)*Mimg + p2] = v11;
            }
        }
    }
}

// ---------------- warp-MMA 3x3 conv, 3-stage pipeline ----------------
__global__ void __launch_bounds__(256)
conv3x3_wmma(const __nv_bfloat16* __restrict__ sh, const __nv_bfloat16* __restrict__ sl,
             const __nv_bfloat16* __restrict__ wh, const __nv_bfloat16* __restrict__ wl,
             const float* __restrict__ bias, float* __restrict__ out,
             int Cin, int Cout, int NT, int NP)
{
    extern __shared__ char dyn[];
    unsigned sm0 = s2u(dyn);
    int tid = threadIdx.x, lane = tid & 31, warp = tid >> 5;
    int wm = warp >> 1, wn = warp & 1;
    int warpN = NT >> 1, nfrags = warpN >> 3;
    int y0 = blockIdx.x * 4, ocb = blockIdx.y * NT, b = blockIdx.z;
    int cpt = Cin >> 5;
    int nch = 9 * cpt;
    int nb = NT >> 3;
    float acc[2][4][4];
#pragma unroll
    for (int mf = 0; mf < 2; mf++)
#pragma unroll
        for (int nf = 0; nf < 4; nf++)
#pragma unroll
            for (int j = 0; j < 4; j++) acc[mf][nf][j] = 0.f;
    int sub = lane >> 3, r = lane & 7;

    auto LD = [&](int c) {
        int tap = c / cpt, cc = c - tap*cpt;
        int ky = tap / 3, kx = tap % 3;
        size_t gbase = ((size_t)kx * NP + (size_t)b * Cin + cc*32) * 1088;
        unsigned base = sm0 + (c % 3) * BUFB;
        for (int i = tid; i < 512; i += 256) {
            int ci = i >> 4, q = i & 15;
            size_t go = gbase + (size_t)ci * 1088 + (size_t)(y0 + ky) * 32 + q*8;
            cpa16(base + ci*272 + q*16, sh + go);
            cpa16(base + AL_OFF + ci*272 + q*16, sl + go);
        }
        for (int i = tid; i < 32*nb; i += 256) {
            int ci = i / nb, q = i % nb;
            size_t wsrc = ((size_t)tap * Cin + cc*32 + ci) * Cout + ocb + q*8;
            cpa16(base + BH_OFF + ci*144 + q*16, wh + wsrc);
            cpa16(base + BL_OFF + ci*144 + q*16, wl + wsrc);
        }
    };

    LD(0); cpa_commit();
    LD(1); cpa_commit();
    for (int c = 0; c < nch; c++) {
        if (c + 1 < nch) cpa_wait1(); else cpa_wait0();
        __syncthreads();
        if (c + 2 < nch) { LD(c + 2); cpa_commit(); }
        unsigned aHb = sm0 + (c % 3)*BUFB, aLb = aHb + AL_OFF, bHb = aHb + BH_OFF, bLb = aHb + BL_OFF;
        MMA_BODY(aHb, aLb, bHb, bLb)
        __syncthreads();
    }

    int g = lane >> 2, tig = lane & 3;
    float* ob = out + (size_t)b * Cout * 1024;
#pragma unroll
    for (int mf = 0; mf < 2; mf++) {
        int m1 = wm*32 + mf*16 + g;
        int m2 = m1 + 8;
        int p1 = (y0 + (m1 >> 5))*32 + (m1 & 31);
        int p2 = (y0 + (m2 >> 5))*32 + (m2 & 31);
#pragma unroll
        for (int nf = 0; nf < 4; nf++) {
            if (nf < nfrags) {
                int n0 = ocb + wn*warpN + nf*8 + 2*tig;
                float b0 = bias ? bias[n0] : 0.f;
                float b1 = bias ? bias[n0+1] : 0.f;
                ob[(size_t)n0*1024 + p1]     = acc[mf][nf][0] + b0;
                ob[(size_t)(n0+1)*1024 + p1] = acc[mf][nf][1] + b1;
                ob[(size_t)n0*1024 + p2]     = acc[mf][nf][2] + b0;
                ob[(size_t)(n0+1)*1024 + p2] = acc[mf][nf][3] + b1;
            }
        }
    }
}

// ---------------- dt1 convT via parity GEMMs, 3-stage pipeline ----------------
__global__ void __launch_bounds__(256)
convt_wmma(const __nv_bfloat16* __restrict__ sh, const __nv_bfloat16* __restrict__ sl,
           const __nv_bfloat16* __restrict__ wh, const __nv_bfloat16* __restrict__ wl,
           const float* __restrict__ bias, float* __restrict__ out, int NP)
{
    extern __shared__ char dyn[];
    unsigned sm0 = s2u(dyn);
    int tid = threadIdx.x, lane = tid & 31, warp = tid >> 5;
    int wm = warp >> 1, wn = warp & 1;
    const int warpN = 32, nfrags = 4, nb = 8;
    int y0 = blockIdx.x * 4, p = blockIdx.y, b = blockIdx.z;
    int py = p >> 1, px = p & 1;
    const int Cin = 128, nch = 16;
    float acc[2][4][4];
#pragma unroll
    for (int mf = 0; mf < 2; mf++)
#pragma unroll
        for (int nf = 0; nf < 4; nf++)
#pragma unroll
            for (int j = 0; j < 4; j++) acc[mf][nf][j] = 0.f;
    int sub = lane >> 3, r = lane & 7;

    auto LD = [&](int c) {
        int t = c >> 2, cc = c & 3;
        int tyi = t >> 1, txi = t & 1;
        int rowoff = tyi + py;
        int plane = txi + px;
        size_t gbase = ((size_t)plane * NP + (size_t)b * Cin + cc*32) * 1088;
        unsigned base = sm0 + (c % 3) * BUFB;
        for (int i = tid; i < 512; i += 256) {
            int ci = i >> 4, q = i & 15;
            size_t go = gbase + (size_t)ci * 1088 + (size_t)(y0 + rowoff) * 32 + q*8;
            cpa16(base + ci*272 + q*16, sh + go);
            cpa16(base + AL_OFF + ci*272 + q*16, sl + go);
        }
        for (int i = tid; i < 32*nb; i += 256) {
            int ci = i / nb, q = i % nb;
            size_t wsrc = ((size_t)(p*4 + t) * 128 + cc*32 + ci) * 64 + q*8;
            cpa16(base + BH_OFF + ci*144 + q*16, wh + wsrc);
            cpa16(base + BL_OFF + ci*144 + q*16, wl + wsrc);
        }
    };

    LD(0); cpa_commit();
    LD(1); cpa_commit();
    for (int c = 0; c < nch; c++) {
        if (c + 1 < nch) cpa_wait1(); else cpa_wait0();
        __syncthreads();
        if (c + 2 < nch) { LD(c + 2); cpa_commit(); }
        unsigned aHb = sm0 + (c % 3)*BUFB, aLb = aHb + AL_OFF, bHb = aHb + BH_OFF, bLb = aHb + BL_OFF;
        MMA_BODY(aHb, aLb, bHb, bLb)
        __syncthreads();
    }

    int g = lane >> 2, tig = lane & 3;
    float* ob = out + (size_t)b * 64 * 4096;
#pragma unroll
    for (int mf = 0; mf < 2; mf++) {
        int m1 = wm*32 + mf*16 + g;
        int m2 = m1 + 8;
#pragma unroll
        for (int mm = 0; mm < 2; mm++) {
            int m = mm ? m2 : m1;
            int y = y0 + (m >> 5), x = m & 31;
            int opix = (2*y + py)*64 + 2*x + px;
#pragma unroll
            for (int nf = 0; nf < 4; nf++) {
                int n0 = wn*warpN + nf*8 + 2*tig;
                float v0 = acc[mf][nf][mm*2 + 0] + bias[n0];
                float v1 = acc[mf][nf][mm*2 + 1] + bias[n0+1];
                ob[(size_t)n0*4096 + opix]     = fmaxf(v0, 0.f);
                ob[(size_t)(n0+1)*4096 + opix] = fmaxf(v1, 0.f);
            }
        }
    }
}

// ---------------- conv 1x1: relu(in) @ w, +bias, +res ----------------
__global__ void __launch_bounds__(256, 3)
conv1x1_f2_kernel(const float* __restrict__ in, const float* __restrict__ w,
                  const float* __restrict__ bias, const float* __restrict__ hres,
                  float* __restrict__ out, int Cin, int Cout)
{
    __shared__ ull s_w[128][16];
    int tid = threadIdx.x;
    int pos = tid & 63, ocg = tid >> 6;
    int s0 = blockIdx.x * 256 + pos * 4;
    int ocb = blockIdx.y * 32;
    int b = blockIdx.z;
    float* swf = (float*)s_w;
    for (int i = tid; i < Cin * 32; i += 256) {
        int ocl = i / Cin; int ci = i % Cin;
        swf[ci*32 + ocl] = w[(ocb + ocl)*Cin + ci];
    }
    __syncthreads();
    ull acc[4][4];
#pragma unroll
    for (int p = 0; p < 4; p++)
#pragma unroll
        for (int j = 0; j < 4; j++) acc[p][j] = 0ull;

    for (int ci = 0; ci < Cin; ci++) {
        float4 iv = *(const float4*)&in[((size_t)(b*Cin + ci) << 10) + s0];
        ull b0 = bc2(fmaxf(iv.x, 0.f)), b1 = bc2(fmaxf(iv.y, 0.f));
        ull b2 = bc2(fmaxf(iv.z, 0.f)), b3 = bc2(fmaxf(iv.w, 0.f));
        ull wr[4];
#pragma unroll
        for (int j = 0; j < 4; j++) wr[j] = s_w[ci][ocg*4 + j];
#pragma unroll
        for (int j = 0; j < 4; j++) {
            ffma2(acc[0][j], b0, wr[j]);
            ffma2(acc[1][j], b1, wr[j]);
            ffma2(acc[2][j], b2, wr[j]);
            ffma2(acc[3][j], b3, wr[j]);
        }
    }
#pragma unroll
    for (int j = 0; j < 4; j++) {
#pragma unroll
        for (int lane = 0; lane < 2; lane++) {
            int oc = ocb + ocg*8 + 2*j + lane;
            size_t base = (((size_t)b*Cout + oc) << 10) + s0;
            float bv = bias ? bias[oc] : 0.f;
            float4 hv = make_float4(0.f, 0.f, 0.f, 0.f);
            if (hres) hv = *(const float4*)&hres[base];
            float4 ov;
            ov.x = (lane ? hi32(acc[0][j]) : lo32(acc[0][j])) + bv + hv.x;
            ov.y = (lane ? hi32(acc[1][j]) : lo32(acc[1][j])) + bv + hv.y;
            ov.z = (lane ? hi32(acc[2][j]) : lo32(acc[2][j])) + bv + hv.z;
            ov.w = (lane ? hi32(acc[3][j]) : lo32(acc[3][j])) + bv + hv.w;
            *(float4*)&out[base] = ov;
        }
    }
}

// ---------------- vector quantizer, fused Q plane staging ----------------
__global__ void vq_kernel(const float* __restrict__ z, const float* __restrict__ cb,
                          int* __restrict__ hist, float* __restrict__ ssep,
                          __nv_bfloat16* sgh, __nv_bfloat16* sgl)
{
    __shared__ ull s_cb[128][32];
    __shared__ float s_cn[128];
    __shared__ int s_hist[512];
    __shared__ float s_red[128];
    int tid = threadIdx.x;
    for (int i = tid; i < 512; i += 128) s_hist[i] = 0;

    int n = blockIdx.x * 128 + tid;
    int b = n >> 10, s = n & 1023;
    ull zp[32];
    float zv[64];
#pragma unroll
    for (int d = 0; d < 64; d++) zv[d] = z[(((size_t)b * 64 + d) << 10) + s];
#pragma unroll
    for (int j = 0; j < 32; j++) zp[j] = pack2(zv[2*j], zv[2*j+1]);

    const ull* cbu = (const ull*)cb;
    float best = 3.4e38f; int bi = 0;
    for (int k0 = 0; k0 < 512; k0 += 128) {
        __syncthreads();
        for (int i = tid; i < 128*32; i += 128)
            s_cb[i >> 5][i & 31] = cbu[((size_t)k0 << 5) + i];
        __syncthreads();
        {
            float cn = 0.f;
#pragma unroll
            for (int j = 0; j < 32; j++) {
                ull p = s_cb[tid][j];
                float a = lo32(p), bb = hi32(p);
                cn += a*a + bb*bb;
            }
            s_cn[tid] = cn;
        }
        __syncthreads();
        for (int k = 0; k < 128; k++) {
            ull dp = 0ull;
#pragma unroll
            for (int j = 0; j < 32; j++) ffma2(dp, zp[j], s_cb[k][j]);
            float dot = lo32(dp) + hi32(dp);
            float dd = s_cn[k] - 2.f * dot;
            if (dd < best) { best = dd; bi = k0 + k; }
        }
    }
    float sq = 0.f;
    const float* c = cb + ((size_t)bi << 6);
    int y = s >> 5, x = s & 31;
#pragma unroll
    for (int d = 0; d < 64; d++) {
        float cv = c[d];
        stage_px(sgh, sgl, b*64 + d, y, x, cv);
        float df = cv - zv[d];
        sq += df * df;
    }
    atomicAdd(&s_hist[bi], 1);
    s_red[tid] = sq;
    __syncthreads();
    for (int st = 64; st > 0; st >>= 1) {
        if (tid < st) s_red[tid] += s_red[tid + st];
        __syncthreads();
    }
    if (tid == 0) ssep[blockIdx.x] = s_red[0];
    for (int i = tid; i < 512; i += 128)
        if (s_hist[i]) atomicAdd(&hist[i], s_hist[i]);
}

// ---------------- dt2: convT (64->3), 4-oc scalar ----------------
__global__ void convt4s2_kernel(const float* __restrict__ in, const float* __restrict__ w,
                                const float* __restrict__ bias, float* __restrict__ out,
                                int Cin, int Hin, int Win, int Cout, int inRelu, int outRelu)
{
    __shared__ float s_in[8][10][12];
    __shared__ float s_w[4][8][16];
    int tid = threadIdx.x;
    int Hout = Hin * 2, Wout = Win * 2;
    int ntx = Wout >> 4;
    int ox0 = (blockIdx.x % ntx) << 4, oy0 = (blockIdx.x / ntx) << 4;
    int b = blockIdx.z;
    int px = tid & 15, py = tid >> 4;
    int iy0 = oy0 >> 1, ix0 = ox0 >> 1;
    float acc[4];
#pragma unroll
    for (int i = 0; i < 4; i++) acc[i] = 0.f;

    for (int c0 = 0; c0 < Cin; c0 += 8) {
        for (int i = tid; i < 8 * 10 * 10; i += 256) {
            int ci = i / 100; int rr = (i / 10) % 10; int col = i % 10;
            int gy = iy0 - 1 + rr, gx = ix0 - 1 + col;
            float v = 0.f;
            if ((unsigned)gy < (unsigned)Hin && (unsigned)gx < (unsigned)Win)
                v = in[((b*Cin + c0 + ci)*Hin + gy)*Win + gx];
            if (inRelu) v = fmaxf(v, 0.f);
            s_in[ci][rr][col] = v;
        }
        for (int i = tid; i < 4 * 8 * 16; i += 256) {
            int oc = i >> 7; int ci = (i >> 4) & 7; int k = i & 15;
            s_w[oc][ci][k] = (oc < Cout) ? w[((size_t)oc * Cin + c0 + ci)*16 + k] : 0.f;
        }
        __syncthreads();
        int ky0 = py & 1, kx0 = px & 1;
        int r0 = (py + ky0) >> 1;
        int q0 = (px + kx0) >> 1;
#pragma unroll
        for (int ci = 0; ci < 8; ci++) {
            float v00 = s_in[ci][r0][q0];
            float v01 = s_in[ci][r0][q0 + 1];
            float v10 = s_in[ci][r0 + 1][q0];
            float v11 = s_in[ci][r0 + 1][q0 + 1];
#pragma unroll
            for (int oc = 0; oc < 4; oc++) {
                float a = acc[oc];
                a += v00 * s_w[oc][ci][ky0*4 + kx0];
                a += v01 * s_w[oc][ci][ky0*4 + kx0 + 2];
                a += v10 * s_w[oc][ci][(ky0+2)*4 + kx0];
                a += v11 * s_w[oc][ci][(ky0+2)*4 + kx0 + 2];
                acc[oc] = a;
            }
        }
        __syncthreads();
    }
#pragma unroll
    for (int oc = 0; oc < 4; oc++) {
        if (oc < Cout) {
            float r = acc[oc] + bias[oc];
            if (outRelu) r = fmaxf(r, 0.f);
            out[(((size_t)b * Cout + oc)*Hout + oy0 + py)*Wout + ox0 + px] = r;
        }
    }
}

// ---------------- finalize ----------------
__global__ void finalize_kernel(const int* __restrict__ hist, const float* __restrict__ ssep,
                                float* __restrict__ out, int lastIdx)
{
    __shared__ float red[512];
    __shared__ float red2[256];
    int t = threadIdx.x;
    float p = hist[t] * (1.0f / 32768.0f);
    red[t] = p * logf(p + 1e-10f);
    if (t < 256) red2[t] = ssep[t];
    __syncthreads();
    for (int st = 256; st > 0; st >>= 1) {
        if (t < st) red[t] += red[t + st];
        __syncthreads();
    }
    for (int st = 128; st > 0; st >>= 1) {
        if (t < st) red2[t] += red2[t + st];
        __syncthreads();
    }
    if (t == 0) {
        out[0] = red2[0] * 1.25f / (32768.0f * 64.0f);
        out[lastIdx] = expf(-red[0]);
    }
}

// ---------------- launch ----------------
extern "C" void kernel_launch(void* const* d_in, const int* in_sizes, int n_in,
                              void* d_out, int out_size)
{
    const float* x     = (const float*)d_in[0];
    const float* e_w1  = (const float*)d_in[1];
    const float* e_b1  = (const float*)d_in[2];
    const float* e_w2  = (const float*)d_in[3];
    const float* e_b2  = (const float*)d_in[4];
    const float* e_w3  = (const float*)d_in[5];
    const float* e_b3  = (const float*)d_in[6];
    const float* e_r1a = (const float*)d_in[7];
    const float* e_r1b = (const float*)d_in[8];
    const float* e_r2a = (const float*)d_in[9];
    const float* e_r2b = (const float*)d_in[10];
    const float* pre_w = (const float*)d_in[11];
    const float* pre_b = (const float*)d_in[12];
    const float* cb    = (const float*)d_in[13];
    const float* d_w1  = (const float*)d_in[14];
    const float* d_b1  = (const float*)d_in[15];
    const float* d_r1a = (const float*)d_in[16];
    const float* d_r1b = (const float*)d_in[17];
    const float* d_r2a = (const float*)d_in[18];
    const float* d_r2b = (const float*)d_in[19];
    const float* dt_w1 = (const float*)d_in[20];
    const float* dt_b1 = (const float*)d_in[21];
    const float* dt_w2 = (const float*)d_in[22];
    const float* dt_b2 = (const float*)d_in[23];
    float* out = (float*)d_out;

    float *A, *Bb, *C, *R, *Z, *ssep; int* hist;
    __nv_bfloat16 *Sh, *Sl, *Gh, *Gl;
    __nv_bfloat16 *W1h,*W1l,*W2h,*W2l,*W3h,*W3l,*W4h,*W4l,*W5h,*W5l,*W6h,*W6l,*W7h,*W7l,*W8h,*W8l,*W9h,*W9l;
    cudaGetSymbolAddress((void**)&A,    g_A);
    cudaGetSymbolAddress((void**)&Bb,   g_B);
    cudaGetSymbolAddress((void**)&C,    g_C);
    cudaGetSymbolAddress((void**)&R,    g_R);
    cudaGetSymbolAddress((void**)&Z,    g_Z);
    cudaGetSymbolAddress((void**)&ssep, g_ssep);
    cudaGetSymbolAddress((void**)&hist, g_hist);
    cudaGetSymbolAddress((void**)&Sh,   g_Sh);
    cudaGetSymbolAddress((void**)&Sl,   g_Sl);
    cudaGetSymbolAddress((void**)&Gh,   g_Gh);
    cudaGetSymbolAddress((void**)&Gl,   g_Gl);
    cudaGetSymbolAddress((void**)&W1h,  g_W1h); cudaGetSymbolAddress((void**)&W1l, g_W1l);
    cudaGetSymbolAddress((void**)&W2h,  g_W2h); cudaGetSymbolAddress((void**)&W2l, g_W2l);
    cudaGetSymbolAddress((void**)&W3h,  g_W3h); cudaGetSymbolAddress((void**)&W3l, g_W3l);
    cudaGetSymbolAddress((void**)&W4h,  g_W4h); cudaGetSymbolAddress((void**)&W4l, g_W4l);
    cudaGetSymbolAddress((void**)&W5h,  g_W5h); cudaGetSymbolAddress((void**)&W5l, g_W5l);
    cudaGetSymbolAddress((void**)&W6h,  g_W6h); cudaGetSymbolAddress((void**)&W6l, g_W6l);
    cudaGetSymbolAddress((void**)&W7h,  g_W7h); cudaGetSymbolAddress((void**)&W7l, g_W7l);
    cudaGetSymbolAddress((void**)&W8h,  g_W8h); cudaGetSymbolAddress((void**)&W8l, g_W8l);
    cudaGetSymbolAddress((void**)&W9h,  g_W9h); cudaGetSymbolAddress((void**)&W9l, g_W9l);

    static int smem_set = 0;
    if (!smem_set) {
        cudaFuncSetAttribute(gemm_wmma, cudaFuncAttributeMaxDynamicSharedMemorySize, DYN_SMEM);
        cudaFuncSetAttribute(conv3x3_wmma, cudaFuncAttributeMaxDynamicSharedMemorySize, DYN_SMEM);
        cudaFuncSetAttribute(convt_wmma, cudaFuncAttributeMaxDynamicSharedMemorySize, DYN_SMEM);
        smem_set = 1;
    }

    zero_kernel<<<2, 256>>>(hist);
    stage_all_w<<<dim3(16, 9), 256>>>(e_w1, e_w2, e_w3, e_r1a, e_r2a, d_w1, d_r1a, d_r2a, dt_w1);

    // ---- encoder ----
    stage_im2col<<<dim3(64, 8), 256>>>(x, Gh, Gl, 3, 4, 128, 128, 4, 2, 1, 64, 64, BATCH*4096);
    gemm_wmma<<<dim3(1024, 1), 256, DYN_SMEM>>>(Gh, Gl, W1h, W1l, e_b1, A, 64, 64, 64, BATCH*4096, 4096, 1);
    stage_k4s2<<<2048, 256>>>(A, Gh, Gl, BATCH*1024);
    gemm_wmma<<<dim3(256, 2), 256, DYN_SMEM>>>(Gh, Gl, W2h, W2l, e_b2, Bb, 1024, 128, 64, BATCH*1024, 1024, 1);

    stage_in_kernel<<<4096, 256>>>(Bb, Sh, Sl, NPU, 0);
    conv3x3_wmma<<<dim3(8, 2, BATCH), 256, DYN_SMEM>>>(Sh, Sl, W3h, W3l, e_b3, C, 128, 128, 64, NPU);
    stage_in_kernel<<<4096, 256>>>(C, Sh, Sl, NPU, 1);
    conv3x3_wmma<<<dim3(8, 1, BATCH), 256, DYN_SMEM>>>(Sh, Sl, W4h, W4l, nullptr, R, 128, 32, 32, NPU);
    conv1x1_f2_kernel<<<dim3(4, 4, BATCH), 256>>>(R, e_r1b, nullptr, C, C, 32, 128);
    stage_in_kernel<<<4096, 256>>>(C, Sh, Sl, NPU, 1);
    conv3x3_wmma<<<dim3(8, 1, BATCH), 256, DYN_SMEM>>>(Sh, Sl, W5h, W5l, nullptr, R, 128, 32, 32, NPU);
    conv1x1_f2_kernel<<<dim3(4, 4, BATCH), 256>>>(R, e_r2b, nullptr, C, C, 32, 128);
    conv1x1_f2_kernel<<<dim3(4, 2, BATCH), 256>>>(C, pre_w, pre_b, nullptr, Z, 128, 64);

    // ---- VQ (fused Q plane staging into S) ----
    vq_kernel<<<256, 128>>>(Z, cb, hist, ssep, Sh, Sl);

    // ---- decoder ----
    conv3x3_wmma<<<dim3(8, 2, BATCH), 256, DYN_SMEM>>>(Sh, Sl, W6h, W6l, d_b1, Bb, 64, 128, 64, NPU);
    stage_in_kernel<<<4096, 256>>>(Bb, Sh, Sl, NPU, 1);
    conv3x3_wmma<<<dim3(8, 1, BATCH), 256, DYN_SMEM>>>(Sh, Sl, W7h, W7l, nullptr, R, 128, 32, 32, NPU);
    conv1x1_f2_kernel<<<dim3(4, 4, BATCH), 256>>>(R, d_r1b, nullptr, Bb, Bb, 32, 128);
    stage_in_kernel<<<4096, 256>>>(Bb, Sh, Sl, NPU, 1);
    conv3x3_wmma<<<dim3(8, 1, BATCH), 256, DYN_SMEM>>>(Sh, Sl, W8h, W8l, nullptr, R, 128, 32, 32, NPU);
    conv1x1_f2_kernel<<<dim3(4, 4, BATCH), 256>>>(R, d_r2b, nullptr, Bb, Bb, 32, 128);

    stage_in_kernel<<<4096, 256>>>(Bb, Sh, Sl, NPU, 1);
    convt_wmma<<<dim3(8, 4, BATCH), 256, DYN_SMEM>>>(Sh, Sl, W9h, W9l, dt_b1, A, NPU);

    convt4s2_kernel<<<dim3(64, 1, BATCH), 256>>>(A, dt_w2, dt_b2, out + 1, 64, 64, 64, 3, 0, 0);

    finalize_kernel<<<1, 512>>>(hist, ssep, out, out_size - 1);
}

// round 16
// speedup vs baseline: 1.1631x; 1.0429x over previous
#include <cuda_runtime.h>
#include <cuda_bf16.h>
#include <math.h>

typedef unsigned long long ull;

// ---------------- packed f32x2 helpers ----------------
__device__ __forceinline__ ull pack2(float lo, float hi) {
    ull r; asm("mov.b64 %0, {%1, %2};" : "=l"(r) : "f"(lo), "f"(hi)); return r;
}
__device__ __forceinline__ ull bc2(float v) { return pack2(v, v); }
__device__ __forceinline__ void ffma2(ull& d, ull a, ull b) {
    asm("fma.rn.f32x2 %0, %1, %2, %0;" : "+l"(d) : "l"(a), "l"(b));
}
__device__ __forceinline__ float lo32(ull v) { return __uint_as_float((unsigned)v); }
__device__ __forceinline__ float hi32(ull v) { return __uint_as_float((unsigned)(v >> 32)); }

// ---------------- mma.sync / cp.async helpers ----------------
__device__ __forceinline__ unsigned s2u(const void* p) {
    unsigned a; asm("{ .reg .u64 t; cvta.to.shared.u64 t, %1; cvt.u32.u64 %0, t; }" : "=r"(a) : "l"(p));
    return a;
}
__device__ __forceinline__ void ldsm4t(unsigned* r, unsigned addr) {
    asm volatile("ldmatrix.sync.aligned.m8n8.x4.trans.shared.b16 {%0,%1,%2,%3}, [%4];"
                 : "=r"(r[0]), "=r"(r[1]), "=r"(r[2]), "=r"(r[3]) : "r"(addr));
}
__device__ __forceinline__ void mma16816(float* c, const unsigned* a, const unsigned* b) {
    asm volatile(
        "mma.sync.aligned.m16n8k16.row.col.f32.bf16.bf16.f32 "
        "{%0,%1,%2,%3}, {%4,%5,%6,%7}, {%8,%9}, {%0,%1,%2,%3};"
        : "+f"(c[0]), "+f"(c[1]), "+f"(c[2]), "+f"(c[3])
        : "r"(a[0]), "r"(a[1]), "r"(a[2]), "r"(a[3]), "r"(b[0]), "r"(b[1]));
}
__device__ __forceinline__ void cpa16(unsigned saddr, const void* g) {
    asm volatile("cp.async.cg.shared.global [%0], [%1], 16;" :: "r"(saddr), "l"(g));
}
__device__ __forceinline__ void cpa_commit() { asm volatile("cp.async.commit_group;" ::: "memory"); }
__device__ __forceinline__ void cpa_wait0() { asm volatile("cp.async.wait_group 0;" ::: "memory"); }
__device__ __forceinline__ void cpa_wait1() { asm volatile("cp.async.wait_group 1;" ::: "memory"); }

#define BUFB 26624
#define AL_OFF 8704
#define BH_OFF 17408
#define BL_OFF 22016
#define DYN_SMEM (3*26624)
#define NPU 4096

// ---------------- scratch ----------------
#define BATCH 32
__device__ float g_A[BATCH*64*64*64];
__device__ float g_B[BATCH*128*32*32];
__device__ float g_C[BATCH*128*32*32];
__device__ float g_Z[BATCH*64*32*32];
__device__ int   g_hist[512];
__device__ float g_ssep[256];
__device__ __align__(16) __nv_bfloat16 g_Sh[3*4096*1088];
__device__ __align__(16) __nv_bfloat16 g_Sl[3*4096*1088];
__device__ __align__(16) __nv_bfloat16 g_Gh[1024*32768];
__device__ __align__(16) __nv_bfloat16 g_Gl[1024*32768];
// per-layer staged weights
__device__ __align__(16) __nv_bfloat16 g_W1h[64*64],      g_W1l[64*64];
__device__ __align__(16) __nv_bfloat16 g_W2h[1024*128],   g_W2l[1024*128];
__device__ __align__(16) __nv_bfloat16 g_W3h[9*128*128],  g_W3l[9*128*128];
__device__ __align__(16) __nv_bfloat16 g_W4h[9*128*32],   g_W4l[9*128*32];
__device__ __align__(16) __nv_bfloat16 g_W5h[9*128*32],   g_W5l[9*128*32];
__device__ __align__(16) __nv_bfloat16 g_W6h[9*64*128],   g_W6l[9*64*128];
__device__ __align__(16) __nv_bfloat16 g_W7h[9*128*32],   g_W7l[9*128*32];
__device__ __align__(16) __nv_bfloat16 g_W8h[9*128*32],   g_W8l[9*128*32];
__device__ __align__(16) __nv_bfloat16 g_W9h[16*128*64],  g_W9l[16*128*64];

__global__ void zero_kernel(int* hist) {
    int t = blockIdx.x * blockDim.x + threadIdx.x;
    if (t < 512) hist[t] = 0;
}

// scatter one pixel into the 3 kx-shifted split-bf16 planes (interior only)
__device__ __forceinline__ void stage_px(__nv_bfloat16* sh, __nv_bfloat16* sl,
                                         int plane, int y, int x, float v)
{
    __nv_bfloat16 h = __float2bfloat16(v);
    __nv_bfloat16 l = __float2bfloat16(v - __bfloat162float(h));
    size_t rowbase = (size_t)plane * 1088 + (size_t)(y + 1) * 32;
#pragma unroll
    for (int kx = 0; kx < 3; kx++) {
        int c = x - kx + 1;
        if ((unsigned)c < 32u) {
            size_t o = (size_t)kx * ((size_t)NPU*1088) + rowbase + c;
            sh[o] = h; sl[o] = l;
        }
    }
}

// ---------------- stage input (shifted planes) ----------------
__global__ void stage_in_kernel(const float* __restrict__ in, __nv_bfloat16* __restrict__ sh,
                                __nv_bfloat16* __restrict__ sl, int NP, int doRelu)
{
    int plane = blockIdx.x;
    const float* src = in + (size_t)plane * 1024;
    for (int i = threadIdx.x; i < 3*1088; i += 256) {
        int kx = i / 1088; int r = (i % 1088) / 32; int c = i & 31;
        float v = 0.f;
        int sy = r - 1, sx = c + kx - 1;
        if ((unsigned)sy < 32u && (unsigned)sx < 32u) v = src[sy*32 + sx];
        if (doRelu) v = fmaxf(v, 0.f);
        __nv_bfloat16 h = __float2bfloat16(v);
        __nv_bfloat16 l = __float2bfloat16(v - __bfloat162float(h));
        size_t o = ((size_t)kx * NP + plane) * 1088 + r*32 + c;
        sh[o] = h; sl[o] = l;
    }
}

// ---------------- weight-staging device helpers ----------------
__device__ void dev_w33(const float* w, __nv_bfloat16* wh, __nv_bfloat16* wl,
                        int Cin, int Cout, int i0, int stride)
{
    int n = Cin * Cout * 9;
    for (int i = i0; i < n; i += stride) {
        int oc = i / (Cin*9); int rr = i % (Cin*9); int ci = rr / 9; int t = rr % 9;
        float v = w[i];
        __nv_bfloat16 h = __float2bfloat16(v);
        __nv_bfloat16 l = __float2bfloat16(v - __bfloat162float(h));
        size_t dst = ((size_t)t * Cin + ci) * Cout + oc;
        wh[dst] = h; wl[dst] = l;
    }
}
__device__ void dev_w_gen(const float* w, __nv_bfloat16* wh, __nv_bfloat16* wl,
                          int Cin, int CinP, int Cout, int T, int i0, int stride)
{
    int ntot = T * CinP * Cout;
    for (int i = i0; i < ntot; i += stride) {
        int k = i / Cout, oc = i % Cout;
        int t = k / CinP, ci = k % CinP;
        float v = (ci < Cin) ? w[((size_t)oc*Cin + ci)*T + t] : 0.f;
        __nv_bfloat16 h = __float2bfloat16(v);
        __nv_bfloat16 l = __float2bfloat16(v - __bfloat162float(h));
        wh[(size_t)k*Cout + oc] = h; wl[(size_t)k*Cout + oc] = l;
    }
}
__device__ void dev_w_dt1(const float* w, __nv_bfloat16* wh, __nv_bfloat16* wl,
                          int i0, int stride)
{
    for (int i = i0; i < 4*4*128*64; i += stride) {
        int oc = i & 63, ci = (i >> 6) & 127, t = (i >> 13) & 3, p = i >> 15;
        int ky = 2*(t >> 1) + (p >> 1);
        int kx = 2*(t & 1) + (p & 1);
        float v = w[((size_t)oc*128 + ci)*16 + ky*4 + kx];
        __nv_bfloat16 h = __float2bfloat16(v);
        __nv_bfloat16 l = __float2bfloat16(v - __bfloat162float(h));
        wh[i] = h; wl[i] = l;
    }
}

__global__ void stage_all_w(const float* e_w1, const float* e_w2, const float* e_w3,
                            const float* e_r1a, const float* e_r2a, const float* d_w1,
                            const float* d_r1a, const float* d_r2a, const float* dt_w1)
{
    int i0 = blockIdx.x * 256 + threadIdx.x;
    int stride = gridDim.x * 256;
    switch (blockIdx.y) {
    case 0: dev_w_gen(e_w1, g_W1h, g_W1l, 3, 4, 64, 16, i0, stride); break;
    case 1: dev_w_gen(e_w2, g_W2h, g_W2l, 64, 64, 128, 16, i0, stride); break;
    case 2: dev_w33(e_w3,  g_W3h, g_W3l, 128, 128, i0, stride); break;
    case 3: dev_w33(e_r1a, g_W4h, g_W4l, 128, 32, i0, stride); break;
    case 4: dev_w33(e_r2a, g_W5h, g_W5l, 128, 32, i0, stride); break;
    case 5: dev_w33(d_w1,  g_W6h, g_W6l, 64, 128, i0, stride); break;
    case 6: dev_w33(d_r1a, g_W7h, g_W7l, 128, 32, i0, stride); break;
    case 7: dev_w33(d_r2a, g_W8h, g_W8l, 128, 32, i0, stride); break;
    case 8: dev_w_dt1(dt_w1, g_W9h, g_W9l, i0, stride); break;
    }
}

// ---------------- generic im2col stage (conv1) ----------------
__global__ void stage_im2col(const float* __restrict__ in, __nv_bfloat16* __restrict__ ah,
                             __nv_bfloat16* __restrict__ al,
                             int Cin, int CinP, int Hin, int Win, int KW,
                             int stride, int pad, int Hout, int Wout, int Mtot)
{
    int k = blockIdx.x;
    int t = k / CinP, ci = k % CinP;
    int ky = t / KW, kx = t % KW;
    int Mimg = Hout * Wout;
    __nv_bfloat16* dh = ah + (size_t)k * Mtot;
    __nv_bfloat16* dl = al + (size_t)k * Mtot;
    int seg = Mtot / gridDim.y;
    int mend = seg * (blockIdx.y + 1);
    for (int m = seg * blockIdx.y + threadIdx.x; m < mend; m += 256) {
        int b = m / Mimg, pos = m % Mimg;
        int y = pos / Wout, x = pos % Wout;
        float v = 0.f;
        if (ci < Cin) {
            int iy = y*stride - pad + ky, ix = x*stride - pad + kx;
            if ((unsigned)iy < (unsigned)Hin && (unsigned)ix < (unsigned)Win)
                v = in[((size_t)(b*Cin + ci)*Hin + iy)*Win + ix];
        }
        __nv_bfloat16 h = __float2bfloat16(v);
        __nv_bfloat16 l = __float2bfloat16(v - __bfloat162float(h));
        dh[m] = h; dl[m] = l;
    }
}

// ---------------- read-once tiled im2col for conv2 ----------------
__global__ void stage_k4s2(const float* __restrict__ in, __nv_bfloat16* __restrict__ gh,
                           __nv_bfloat16* __restrict__ gl, int Mtot)
{
    __shared__ float tile[67][68];
    int bci = blockIdx.x;
    const float* src = in + (size_t)bci * 4096;
    for (int i = threadIdx.x; i < 67*67; i += 256) {
        int r = i / 67, c = i % 67;
        float v = 0.f;
        int iy = r - 1, ix = c - 1;
        if ((unsigned)iy < 64u && (unsigned)ix < 64u) v = src[iy*64 + ix];
        tile[r][c] = v;
    }
    __syncthreads();
    int b = bci >> 6, ci = bci & 63;
    for (int i = threadIdx.x; i < 16*1024; i += 256) {
        int t = i >> 10, pos = i & 1023;
        int y = pos >> 5, x = pos & 31;
        int ky = t >> 2, kx = t & 3;
        float v = tile[2*y + ky][2*x + kx];
        __nv_bfloat16 h = __float2bfloat16(v);
        __nv_bfloat16 l = __float2bfloat16(v - __bfloat162float(h));
        size_t dst = ((size_t)(t*64 + ci)) * Mtot + (size_t)b*1024 + pos;
        gh[dst] = h; gl[dst] = l;
    }
}

// ---------------- MMA core macro body ----------------
#define MMA_BODY(aHb, aLb, bHb, bLb)                                              \
    _Pragma("unroll")                                                             \
    for (int kf = 0; kf < 2; kf++) {                                              \
        unsigned Ah[2][4], Al[2][4];                                              \
        int akrow = kf*16 + ((sub & 2) ? 8 : 0) + r;                              \
        int acoff = (sub & 1) ? 8 : 0;                                            \
        _Pragma("unroll")                                                         \
        for (int mf = 0; mf < 2; mf++) {                                          \
            unsigned off = (unsigned)(akrow*272 + (wm*32 + mf*16 + acoff)*2);     \
            ldsm4t(Ah[mf], (aHb) + off);                                          \
            ldsm4t(Al[mf], (aLb) + off);                                          \
        }                                                                         \
        unsigned Bh[4][2], Bl[4][2];                                              \
        int bkrow = kf*16 + ((sub & 1) ? 8 : 0) + r;                              \
        int bcoff = (sub & 2) ? 8 : 0;                                            \
        _Pragma("unroll")                                                         \
        for (int nf2 = 0; nf2 < 4; nf2 += 2) {                                    \
            if (nf2 < nfrags) {                                                   \
                unsigned off = (unsigned)(bkrow*144 + (wn*warpN + nf2*8 + bcoff)*2); \
                unsigned t4[4];                                                   \
                ldsm4t(t4, (bHb) + off);                                          \
                Bh[nf2][0] = t4[0]; Bh[nf2][1] = t4[1];                           \
                Bh[nf2+1][0] = t4[2]; Bh[nf2+1][1] = t4[3];                       \
                ldsm4t(t4, (bLb) + off);                                          \
                Bl[nf2][0] = t4[0]; Bl[nf2][1] = t4[1];                           \
                Bl[nf2+1][0] = t4[2]; Bl[nf2+1][1] = t4[3];                       \
            }                                                                     \
        }                                                                         \
        _Pragma("unroll")                                                         \
        for (int mf = 0; mf < 2; mf++)                                            \
            _Pragma("unroll")                                                     \
            for (int nf = 0; nf < 4; nf++) {                                      \
                if (nf < nfrags) {                                                \
                    mma16816(acc[mf][nf], Ah[mf], Bh[nf]);                        \
                    mma16816(acc[mf][nf], Ah[mf], Bl[nf]);                        \
                    mma16816(acc[mf][nf], Al[mf], Bh[nf]);                        \
                }                                                                 \
            }                                                                     \
    }

// ---------------- generic GEMM, 3-stage pipeline ----------------
__global__ void __launch_bounds__(256)
gemm_wmma(const __nv_bfloat16* __restrict__ ah, const __nv_bfloat16* __restrict__ al,
          const __nv_bfloat16* __restrict__ wh, const __nv_bfloat16* __restrict__ wl,
          const float* __restrict__ bias, float* __restrict__ out,
          int K, int Cout, int NT, int Mtot, int Mimg, int outRelu)
{
    extern __shared__ char dyn[];
    unsigned sm0 = s2u(dyn);
    int tid = threadIdx.x, lane = tid & 31, warp = tid >> 5;
    int wm = warp >> 1, wn = warp & 1;
    int warpN = NT >> 1, nfrags = warpN >> 3;
    int m0 = blockIdx.x * 128, ocb = blockIdx.y * NT;
    int nb = NT >> 3;
    int nch = K >> 5;
    float acc[2][4][4];
#pragma unroll
    for (int mf = 0; mf < 2; mf++)
#pragma unroll
        for (int nf = 0; nf < 4; nf++)
#pragma unroll
            for (int j = 0; j < 4; j++) acc[mf][nf][j] = 0.f;
    int sub = lane >> 3, r = lane & 7;

    auto LD = [&](int c) {
        int kc = c << 5;
        unsigned base = sm0 + (c % 3) * BUFB;
        for (int i = tid; i < 512; i += 256) {
            int kk = i >> 4, q = i & 15;
            size_t go = (size_t)(kc + kk) * Mtot + m0 + q*8;
            cpa16(base + kk*272 + q*16, ah + go);
            cpa16(base + AL_OFF + kk*272 + q*16, al + go);
        }
        for (int i = tid; i < 32*nb; i += 256) {
            int kk = i / nb, q = i % nb;
            size_t wsrc = (size_t)(kc + kk) * Cout + ocb + q*8;
            cpa16(base + BH_OFF + kk*144 + q*16, wh + wsrc);
            cpa16(base + BL_OFF + kk*144 + q*16, wl + wsrc);
        }
    };

    LD(0); cpa_commit();
    if (nch > 1) { LD(1); cpa_commit(); }
    for (int c = 0; c < nch; c++) {
        if (c + 1 < nch) cpa_wait1(); else cpa_wait0();
        __syncthreads();
        if (c + 2 < nch) { LD(c + 2); cpa_commit(); }
        unsigned aHb = sm0 + (c % 3)*BUFB, aLb = aHb + AL_OFF, bHb = aHb + BH_OFF, bLb = aHb + BL_OFF;
        MMA_BODY(aHb, aLb, bHb, bLb)
    }

    int g = lane >> 2, tig = lane & 3;
    int b = m0 / Mimg;
    int base = m0 - b * Mimg;
    float* ob = out + (size_t)b * Cout * Mimg;
#pragma unroll
    for (int mf = 0; mf < 2; mf++) {
        int p1 = base + wm*32 + mf*16 + g;
        int p2 = p1 + 8;
#pragma unroll
        for (int nf = 0; nf < 4; nf++) {
            if (nf < nfrags) {
                int n0 = ocb + wn*warpN + nf*8 + 2*tig;
                float b0 = bias ? bias[n0] : 0.f;
                float b1 = bias ? bias[n0+1] : 0.f;
                float v00 = acc[mf][nf][0] + b0, v01 = acc[mf][nf][1] + b1;
                float v10 = acc[mf][nf][2] + b0, v11 = acc[mf][nf][3] + b1;
                if (outRelu) {
                    v00 = fmaxf(v00, 0.f); v01 = fmaxf(v01, 0.f);
                    v10 = fmaxf(v10, 0.f); v11 = fmaxf(v11, 0.f);
                }
                ob[(size_t)n0*Mimg + p1]     = v00;
                ob[(size_t)(n0+1)*Mimg + p1] = v01;
                ob[(size_t)n0*Mimg + p2]     = v10;
                ob[(size_t)(n0+1)*Mimg + p2] = v11;
            }
        }
    }
}

// ---------------- warp-MMA 3x3 conv, 3-stage pipeline, optional fused res-1x1 ----------------
// When w1x1 != nullptr (requires NT==32): instead of writing R to global, compute
// C' = hres + (w1x1 @ relu(R)) and write to out1x1 (Cout1=128). bias must be null then.
__global__ void __launch_bounds__(256)
conv3x3_wmma(const __nv_bfloat16* __restrict__ sh, const __nv_bfloat16* __restrict__ sl,
             const __nv_bfloat16* __restrict__ wh, const __nv_bfloat16* __restrict__ wl,
             const float* __restrict__ bias, float* __restrict__ out,
             int Cin, int Cout, int NT, int NP,
             const float* __restrict__ w1x1, const float* __restrict__ hres,
             float* __restrict__ out1x1)
{
    extern __shared__ char dyn[];
    unsigned sm0 = s2u(dyn);
    int tid = threadIdx.x, lane = tid & 31, warp = tid >> 5;
    int wm = warp >> 1, wn = warp & 1;
    int warpN = NT >> 1, nfrags = warpN >> 3;
    int y0 = blockIdx.x * 4, ocb = blockIdx.y * NT, b = blockIdx.z;
    int cpt = Cin >> 5;
    int nch = 9 * cpt;
    int nb = NT >> 3;
    float acc[2][4][4];
#pragma unroll
    for (int mf = 0; mf < 2; mf++)
#pragma unroll
        for (int nf = 0; nf < 4; nf++)
#pragma unroll
            for (int j = 0; j < 4; j++) acc[mf][nf][j] = 0.f;
    int sub = lane >> 3, r = lane & 7;

    auto LD = [&](int c) {
        int tap = c / cpt, cc = c - tap*cpt;
        int ky = tap / 3, kx = tap % 3;
        size_t gbase = ((size_t)kx * NP + (size_t)b * Cin + cc*32) * 1088;
        unsigned base = sm0 + (c % 3) * BUFB;
        for (int i = tid; i < 512; i += 256) {
            int ci = i >> 4, q = i & 15;
            size_t go = gbase + (size_t)ci * 1088 + (size_t)(y0 + ky) * 32 + q*8;
            cpa16(base + ci*272 + q*16, sh + go);
            cpa16(base + AL_OFF + ci*272 + q*16, sl + go);
        }
        for (int i = tid; i < 32*nb; i += 256) {
            int ci = i / nb, q = i % nb;
            size_t wsrc = ((size_t)tap * Cin + cc*32 + ci) * Cout + ocb + q*8;
            cpa16(base + BH_OFF + ci*144 + q*16, wh + wsrc);
            cpa16(base + BL_OFF + ci*144 + q*16, wl + wsrc);
        }
    };

    LD(0); cpa_commit();
    LD(1); cpa_commit();
    for (int c = 0; c < nch; c++) {
        if (c + 1 < nch) cpa_wait1(); else cpa_wait0();
        __syncthreads();
        if (c + 2 < nch) { LD(c + 2); cpa_commit(); }
        unsigned aHb = sm0 + (c % 3)*BUFB, aLb = aHb + AL_OFF, bHb = aHb + BH_OFF, bLb = aHb + BL_OFF;
        MMA_BODY(aHb, aLb, bHb, bLb)
    }

    int g = lane >> 2, tig = lane & 3;

    if (w1x1) {
        // ---- fused res 1x1 epilogue (NT==32): C' = hres + w1x1 @ relu(R) ----
        __syncthreads();                          // all MMAs done; smem safe to reuse
        float* sR = (float*)dyn;                  // [128 m][33] = 16896B
        float* sW = (float*)(dyn + 17408);        // [32 ci][128 oc] = 16384B
#pragma unroll
        for (int mf = 0; mf < 2; mf++) {
            int m1 = wm*32 + mf*16 + g;
            int m2 = m1 + 8;
#pragma unroll
            for (int nf = 0; nf < 2; nf++) {
                int n0 = wn*16 + nf*8 + 2*tig;
                sR[m1*33 + n0]     = fmaxf(acc[mf][nf][0], 0.f);
                sR[m1*33 + n0+1]   = fmaxf(acc[mf][nf][1], 0.f);
                sR[m2*33 + n0]     = fmaxf(acc[mf][nf][2], 0.f);
                sR[m2*33 + n0+1]   = fmaxf(acc[mf][nf][3], 0.f);
            }
        }
        for (int i = tid; i < 32*128; i += 256) {
            int oc = i & 127, ci = i >> 7;
            sW[ci*128 + oc] = w1x1[oc*32 + ci];
        }
        __syncthreads();
        int px = tid & 127, half = tid >> 7;
        int pix = (y0 + (px >> 5))*32 + (px & 31);
        ull a2[32];
#pragma unroll
        for (int j = 0; j < 32; j++) a2[j] = 0ull;
        for (int ci = 0; ci < 32; ci++) {
            ull vb = bc2(sR[px*33 + ci]);
            const ull* wrow = (const ull*)(sW + ci*128) + half*32;
#pragma unroll
            for (int j = 0; j < 32; j++) ffma2(a2[j], vb, wrow[j]);
        }
        size_t obase = (size_t)b * 128 * 1024 + (size_t)half * 64 * 1024 + pix;
#pragma unroll
        for (int j = 0; j < 32; j++) {
            size_t o = obase + (size_t)(2*j) * 1024;
            out1x1[o]        = lo32(a2[j]) + hres[o];
            out1x1[o + 1024] = hi32(a2[j]) + hres[o + 1024];
        }
        return;
    }

    float* ob = out + (size_t)b * Cout * 1024;
#pragma unroll
    for (int mf = 0; mf < 2; mf++) {
        int m1 = wm*32 + mf*16 + g;
        int m2 = m1 + 8;
        int p1 = (y0 + (m1 >> 5))*32 + (m1 & 31);
        int p2 = (y0 + (m2 >> 5))*32 + (m2 & 31);
#pragma unroll
        for (int nf = 0; nf < 4; nf++) {
            if (nf < nfrags) {
                int n0 = ocb + wn*warpN + nf*8 + 2*tig;
                float b0 = bias ? bias[n0] : 0.f;
                float b1 = bias ? bias[n0+1] : 0.f;
                ob[(size_t)n0*1024 + p1]     = acc[mf][nf][0] + b0;
                ob[(size_t)(n0+1)*1024 + p1] = acc[mf][nf][1] + b1;
                ob[(size_t)n0*1024 + p2]     = acc[mf][nf][2] + b0;
                ob[(size_t)(n0+1)*1024 + p2] = acc[mf][nf][3] + b1;
            }
        }
    }
}

// ---------------- dt1 convT via parity GEMMs, 3-stage pipeline ----------------
__global__ void __launch_bounds__(256)
convt_wmma(const __nv_bfloat16* __restrict__ sh, const __nv_bfloat16* __restrict__ sl,
           const __nv_bfloat16* __restrict__ wh, const __nv_bfloat16* __restrict__ wl,
           const float* __restrict__ bias, float* __restrict__ out, int NP)
{
    extern __shared__ char dyn[];
    unsigned sm0 = s2u(dyn);
    int tid = threadIdx.x, lane = tid & 31, warp = tid >> 5;
    int wm = warp >> 1, wn = warp & 1;
    const int warpN = 32, nfrags = 4, nb = 8;
    int y0 = blockIdx.x * 4, p = blockIdx.y, b = blockIdx.z;
    int py = p >> 1, px = p & 1;
    const int Cin = 128, nch = 16;
    float acc[2][4][4];
#pragma unroll
    for (int mf = 0; mf < 2; mf++)
#pragma unroll
        for (int nf = 0; nf < 4; nf++)
#pragma unroll
            for (int j = 0; j < 4; j++) acc[mf][nf][j] = 0.f;
    int sub = lane >> 3, r = lane & 7;

    auto LD = [&](int c) {
        int t = c >> 2, cc = c & 3;
        int tyi = t >> 1, txi = t & 1;
        int rowoff = tyi + py;
        int plane = txi + px;
        size_t gbase = ((size_t)plane * NP + (size_t)b * Cin + cc*32) * 1088;
        unsigned base = sm0 + (c % 3) * BUFB;
        for (int i = tid; i < 512; i += 256) {
            int ci = i >> 4, q = i & 15;
            size_t go = gbase + (size_t)ci * 1088 + (size_t)(y0 + rowoff) * 32 + q*8;
            cpa16(base + ci*272 + q*16, sh + go);
            cpa16(base + AL_OFF + ci*272 + q*16, sl + go);
        }
        for (int i = tid; i < 32*nb; i += 256) {
            int ci = i / nb, q = i % nb;
            size_t wsrc = ((size_t)(p*4 + t) * 128 + cc*32 + ci) * 64 + q*8;
            cpa16(base + BH_OFF + ci*144 + q*16, wh + wsrc);
            cpa16(base + BL_OFF + ci*144 + q*16, wl + wsrc);
        }
    };

    LD(0); cpa_commit();
    LD(1); cpa_commit();
    for (int c = 0; c < nch; c++) {
        if (c + 1 < nch) cpa_wait1(); else cpa_wait0();
        __syncthreads();
        if (c + 2 < nch) { LD(c + 2); cpa_commit(); }
        unsigned aHb = sm0 + (c % 3)*BUFB, aLb = aHb + AL_OFF, bHb = aHb + BH_OFF, bLb = aHb + BL_OFF;
        MMA_BODY(aHb, aLb, bHb, bLb)
    }

    int g = lane >> 2, tig = lane & 3;
    float* ob = out + (size_t)b * 64 * 4096;
#pragma unroll
    for (int mf = 0; mf < 2; mf++) {
        int m1 = wm*32 + mf*16 + g;
        int m2 = m1 + 8;
#pragma unroll
        for (int mm = 0; mm < 2; mm++) {
            int m = mm ? m2 : m1;
            int y = y0 + (m >> 5), x = m & 31;
            int opix = (2*y + py)*64 + 2*x + px;
#pragma unroll
            for (int nf = 0; nf < 4; nf++) {
                int n0 = wn*warpN + nf*8 + 2*tig;
                float v0 = acc[mf][nf][mm*2 + 0] + bias[n0];
                float v1 = acc[mf][nf][mm*2 + 1] + bias[n0+1];
                ob[(size_t)n0*4096 + opix]     = fmaxf(v0, 0.f);
                ob[(size_t)(n0+1)*4096 + opix] = fmaxf(v1, 0.f);
            }
        }
    }
}

// ---------------- conv 1x1 (pre-VQ): relu(in) @ w, +bias ----------------
__global__ void __launch_bounds__(256, 3)
conv1x1_f2_kernel(const float* __restrict__ in, const float* __restrict__ w,
                  const float* __restrict__ bias, float* __restrict__ out,
                  int Cin, int Cout)
{
    __shared__ ull s_w[128][16];
    int tid = threadIdx.x;
    int pos = tid & 63, ocg = tid >> 6;
    int s0 = blockIdx.x * 256 + pos * 4;
    int ocb = blockIdx.y * 32;
    int b = blockIdx.z;
    float* swf = (float*)s_w;
    for (int i = tid; i < Cin * 32; i += 256) {
        int ocl = i / Cin; int ci = i % Cin;
        swf[ci*32 + ocl] = w[(ocb + ocl)*Cin + ci];
    }
    __syncthreads();
    ull acc[4][4];
#pragma unroll
    for (int p = 0; p < 4; p++)
#pragma unroll
        for (int j = 0; j < 4; j++) acc[p][j] = 0ull;

    for (int ci = 0; ci < Cin; ci++) {
        float4 iv = *(const float4*)&in[((size_t)(b*Cin + ci) << 10) + s0];
        ull b0 = bc2(fmaxf(iv.x, 0.f)), b1 = bc2(fmaxf(iv.y, 0.f));
        ull b2 = bc2(fmaxf(iv.z, 0.f)), b3 = bc2(fmaxf(iv.w, 0.f));
        ull wr[4];
#pragma unroll
        for (int j = 0; j < 4; j++) wr[j] = s_w[ci][ocg*4 + j];
#pragma unroll
        for (int j = 0; j < 4; j++) {
            ffma2(acc[0][j], b0, wr[j]);
            ffma2(acc[1][j], b1, wr[j]);
            ffma2(acc[2][j], b2, wr[j]);
            ffma2(acc[3][j], b3, wr[j]);
        }
    }
#pragma unroll
    for (int j = 0; j < 4; j++) {
#pragma unroll
        for (int lane = 0; lane < 2; lane++) {
            int oc = ocb + ocg*8 + 2*j + lane;
            size_t base = (((size_t)b*Cout + oc) << 10) + s0;
            float bv = bias ? bias[oc] : 0.f;
            float4 ov;
            ov.x = (lane ? hi32(acc[0][j]) : lo32(acc[0][j])) + bv;
            ov.y = (lane ? hi32(acc[1][j]) : lo32(acc[1][j])) + bv;
            ov.z = (lane ? hi32(acc[2][j]) : lo32(acc[2][j])) + bv;
            ov.w = (lane ? hi32(acc[3][j]) : lo32(acc[3][j])) + bv;
            *(float4*)&out[base] = ov;
        }
    }
}

// ---------------- vector quantizer, fused Q plane staging ----------------
__global__ void vq_kernel(const float* __restrict__ z, const float* __restrict__ cb,
                          int* __restrict__ hist, float* __restrict__ ssep,
                          __nv_bfloat16* sgh, __nv_bfloat16* sgl)
{
    __shared__ ull s_cb[128][32];
    __shared__ float s_cn[128];
    __shared__ int s_hist[512];
    __shared__ float s_red[128];
    int tid = threadIdx.x;
    for (int i = tid; i < 512; i += 128) s_hist[i] = 0;

    int n = blockIdx.x * 128 + tid;
    int b = n >> 10, s = n & 1023;
    ull zp[32];
    float zv[64];
#pragma unroll
    for (int d = 0; d < 64; d++) zv[d] = z[(((size_t)b * 64 + d) << 10) + s];
#pragma unroll
    for (int j = 0; j < 32; j++) zp[j] = pack2(zv[2*j], zv[2*j+1]);

    const ull* cbu = (const ull*)cb;
    float best = 3.4e38f; int bi = 0;
    for (int k0 = 0; k0 < 512; k0 += 128) {
        __syncthreads();
        for (int i = tid; i < 128*32; i += 128)
            s_cb[i >> 5][i & 31] = cbu[((size_t)k0 << 5) + i];
        __syncthreads();
        {
            float cn = 0.f;
#pragma unroll
            for (int j = 0; j < 32; j++) {
                ull p = s_cb[tid][j];
                float a = lo32(p), bb = hi32(p);
                cn += a*a + bb*bb;
            }
            s_cn[tid] = cn;
        }
        __syncthreads();
        for (int k = 0; k < 128; k++) {
            ull dp = 0ull;
#pragma unroll
            for (int j = 0; j < 32; j++) ffma2(dp, zp[j], s_cb[k][j]);
            float dot = lo32(dp) + hi32(dp);
            float dd = s_cn[k] - 2.f * dot;
            if (dd < best) { best = dd; bi = k0 + k; }
        }
    }
    float sq = 0.f;
    const float* c = cb + ((size_t)bi << 6);
    int y = s >> 5, x = s & 31;
#pragma unroll
    for (int d = 0; d < 64; d++) {
        float cv = c[d];
        stage_px(sgh, sgl, b*64 + d, y, x, cv);
        float df = cv - zv[d];
        sq += df * df;
    }
    atomicAdd(&s_hist[bi], 1);
    s_red[tid] = sq;
    __syncthreads();
    for (int st = 64; st > 0; st >>= 1) {
        if (tid < st) s_red[tid] += s_red[tid + st];
        __syncthreads();
    }
    if (tid == 0) ssep[blockIdx.x] = s_red[0];
    for (int i = tid; i < 512; i += 128)
        if (s_hist[i]) atomicAdd(&hist[i], s_hist[i]);
}

// ---------------- dt2: convT (64->3), 4-oc scalar ----------------
__global__ void convt4s2_kernel(const float* __restrict__ in, const float* __restrict__ w,
                                const float* __restrict__ bias, float* __restrict__ out,
                                int Cin, int Hin, int Win, int Cout, int inRelu, int outRelu)
{
    __shared__ float s_in[8][10][12];
    __shared__ float s_w[4][8][16];
    int tid = threadIdx.x;
    int Hout = Hin * 2, Wout = Win * 2;
    int ntx = Wout >> 4;
    int ox0 = (blockIdx.x % ntx) << 4, oy0 = (blockIdx.x / ntx) << 4;
    int b = blockIdx.z;
    int px = tid & 15, py = tid >> 4;
    int iy0 = oy0 >> 1, ix0 = ox0 >> 1;
    float acc[4];
#pragma unroll
    for (int i = 0; i < 4; i++) acc[i] = 0.f;

    for (int c0 = 0; c0 < Cin; c0 += 8) {
        for (int i = tid; i < 8 * 10 * 10; i += 256) {
            int ci = i / 100; int rr = (i / 10) % 10; int col = i % 10;
            int gy = iy0 - 1 + rr, gx = ix0 - 1 + col;
            float v = 0.f;
            if ((unsigned)gy < (unsigned)Hin && (unsigned)gx < (unsigned)Win)
                v = in[((b*Cin + c0 + ci)*Hin + gy)*Win + gx];
            if (inRelu) v = fmaxf(v, 0.f);
            s_in[ci][rr][col] = v;
        }
        for (int i = tid; i < 4 * 8 * 16; i += 256) {
            int oc = i >> 7; int ci = (i >> 4) & 7; int k = i & 15;
            s_w[oc][ci][k] = (oc < Cout) ? w[((size_t)oc * Cin + c0 + ci)*16 + k] : 0.f;
        }
        __syncthreads();
        int ky0 = py & 1, kx0 = px & 1;
        int r0 = (py + ky0) >> 1;
        int q0 = (px + kx0) >> 1;
#pragma unroll
        for (int ci = 0; ci < 8; ci++) {
            float v00 = s_in[ci][r0][q0];
            float v01 = s_in[ci][r0][q0 + 1];
            float v10 = s_in[ci][r0 + 1][q0];
            float v11 = s_in[ci][r0 + 1][q0 + 1];
#pragma unroll
            for (int oc = 0; oc < 4; oc++) {
                float a = acc[oc];
                a += v00 * s_w[oc][ci][ky0*4 + kx0];
                a += v01 * s_w[oc][ci][ky0*4 + kx0 + 2];
                a += v10 * s_w[oc][ci][(ky0+2)*4 + kx0];
                a += v11 * s_w[oc][ci][(ky0+2)*4 + kx0 + 2];
                acc[oc] = a;
            }
        }
        __syncthreads();
    }
#pragma unroll
    for (int oc = 0; oc < 4; oc++) {
        if (oc < Cout) {
            float r = acc[oc] + bias[oc];
            if (outRelu) r = fmaxf(r, 0.f);
            out[(((size_t)b * Cout + oc)*Hout + oy0 + py)*Wout + ox0 + px] = r;
        }
    }
}

// ---------------- finalize ----------------
__global__ void finalize_kernel(const int* __restrict__ hist, const float* __restrict__ ssep,
                                float* __restrict__ out, int lastIdx)
{
    __shared__ float red[512];
    __shared__ float red2[256];
    int t = threadIdx.x;
    float p = hist[t] * (1.0f / 32768.0f);
    red[t] = p * logf(p + 1e-10f);
    if (t < 256) red2[t] = ssep[t];
    __syncthreads();
    for (int st = 256; st > 0; st >>= 1) {
        if (t < st) red[t] += red[t + st];
        __syncthreads();
    }
    for (int st = 128; st > 0; st >>= 1) {
        if (t < st) red2[t] += red2[t + st];
        __syncthreads();
    }
    if (t == 0) {
        out[0] = red2[0] * 1.25f / (32768.0f * 64.0f);
        out[lastIdx] = expf(-red[0]);
    }
}

// ---------------- launch ----------------
extern "C" void kernel_launch(void* const* d_in, const int* in_sizes, int n_in,
                              void* d_out, int out_size)
{
    const float* x     = (const float*)d_in[0];
    const float* e_w1  = (const float*)d_in[1];
    const float* e_b1  = (const float*)d_in[2];
    const float* e_w2  = (const float*)d_in[3];
    const float* e_b2  = (const float*)d_in[4];
    const float* e_w3  = (const float*)d_in[5];
    const float* e_b3  = (const float*)d_in[6];
    const float* e_r1a = (const float*)d_in[7];
    const float* e_r1b = (const float*)d_in[8];
    const float* e_r2a = (const float*)d_in[9];
    const float* e_r2b = (const float*)d_in[10];
    const float* pre_w = (const float*)d_in[11];
    const float* pre_b = (const float*)d_in[12];
    const float* cb    = (const float*)d_in[13];
    const float* d_w1  = (const float*)d_in[14];
    const float* d_b1  = (const float*)d_in[15];
    const float* d_r1a = (const float*)d_in[16];
    const float* d_r1b = (const float*)d_in[17];
    const float* d_r2a = (const float*)d_in[18];
    const float* d_r2b = (const float*)d_in[19];
    const float* dt_w1 = (const float*)d_in[20];
    const float* dt_b1 = (const float*)d_in[21];
    const float* dt_w2 = (const float*)d_in[22];
    const float* dt_b2 = (const float*)d_in[23];
    float* out = (float*)d_out;

    float *A, *Bb, *C, *Z, *ssep; int* hist;
    __nv_bfloat16 *Sh, *Sl, *Gh, *Gl;
    __nv_bfloat16 *W1h,*W1l,*W2h,*W2l,*W3h,*W3l,*W4h,*W4l,*W5h,*W5l,*W6h,*W6l,*W7h,*W7l,*W8h,*W8l,*W9h,*W9l;
    cudaGetSymbolAddress((void**)&A,    g_A);
    cudaGetSymbolAddress((void**)&Bb,   g_B);
    cudaGetSymbolAddress((void**)&C,    g_C);
    cudaGetSymbolAddress((void**)&Z,    g_Z);
    cudaGetSymbolAddress((void**)&ssep, g_ssep);
    cudaGetSymbolAddress((void**)&hist, g_hist);
    cudaGetSymbolAddress((void**)&Sh,   g_Sh);
    cudaGetSymbolAddress((void**)&Sl,   g_Sl);
    cudaGetSymbolAddress((void**)&Gh,   g_Gh);
    cudaGetSymbolAddress((void**)&Gl,   g_Gl);
    cudaGetSymbolAddress((void**)&W1h,  g_W1h); cudaGetSymbolAddress((void**)&W1l, g_W1l);
    cudaGetSymbolAddress((void**)&W2h,  g_W2h); cudaGetSymbolAddress((void**)&W2l, g_W2l);
    cudaGetSymbolAddress((void**)&W3h,  g_W3h); cudaGetSymbolAddress((void**)&W3l, g_W3l);
    cudaGetSymbolAddress((void**)&W4h,  g_W4h); cudaGetSymbolAddress((void**)&W4l, g_W4l);
    cudaGetSymbolAddress((void**)&W5h,  g_W5h); cudaGetSymbolAddress((void**)&W5l, g_W5l);
    cudaGetSymbolAddress((void**)&W6h,  g_W6h); cudaGetSymbolAddress((void**)&W6l, g_W6l);
    cudaGetSymbolAddress((void**)&W7h,  g_W7h); cudaGetSymbolAddress((void**)&W7l, g_W7l);
    cudaGetSymbolAddress((void**)&W8h,  g_W8h); cudaGetSymbolAddress((void**)&W8l, g_W8l);
    cudaGetSymbolAddress((void**)&W9h,  g_W9h); cudaGetSymbolAddress((void**)&W9l, g_W9l);

    static int smem_set = 0;
    if (!smem_set) {
        cudaFuncSetAttribute(gemm_wmma, cudaFuncAttributeMaxDynamicSharedMemorySize, DYN_SMEM);
        cudaFuncSetAttribute(conv3x3_wmma, cudaFuncAttributeMaxDynamicSharedMemorySize, DYN_SMEM);
        cudaFuncSetAttribute(convt_wmma, cudaFuncAttributeMaxDynamicSharedMemorySize, DYN_SMEM);
        smem_set = 1;
    }

    zero_kernel<<<2, 256>>>(hist);
    stage_all_w<<<dim3(16, 9), 256>>>(e_w1, e_w2, e_w3, e_r1a, e_r2a, d_w1, d_r1a, d_r2a, dt_w1);

    // ---- encoder ----
    stage_im2col<<<dim3(64, 8), 256>>>(x, Gh, Gl, 3, 4, 128, 128, 4, 2, 1, 64, 64, BATCH*4096);
    gemm_wmma<<<dim3(1024, 1), 256, DYN_SMEM>>>(Gh, Gl, W1h, W1l, e_b1, A, 64, 64, 64, BATCH*4096, 4096, 1);
    stage_k4s2<<<2048, 256>>>(A, Gh, Gl, BATCH*1024);
    gemm_wmma<<<dim3(256, 2), 256, DYN_SMEM>>>(Gh, Gl, W2h, W2l, e_b2, Bb, 1024, 128, 64, BATCH*1024, 1024, 1);

    stage_in_kernel<<<4096, 256>>>(Bb, Sh, Sl, NPU, 0);
    conv3x3_wmma<<<dim3(8, 2, BATCH), 256, DYN_SMEM>>>(Sh, Sl, W3h, W3l, e_b3, C, 128, 128, 64, NPU,
                                                       nullptr, nullptr, nullptr);
    // res1: 3x3 + fused 1x1 (C -> C)
    stage_in_kernel<<<4096, 256>>>(C, Sh, Sl, NPU, 1);
    conv3x3_wmma<<<dim3(8, 1, BATCH), 256, DYN_SMEM>>>(Sh, Sl, W4h, W4l, nullptr, nullptr, 128, 32, 32, NPU,
                                                       e_r1b, C, C);
    // res2
    stage_in_kernel<<<4096, 256>>>(C, Sh, Sl, NPU, 1);
    conv3x3_wmma<<<dim3(8, 1, BATCH), 256, DYN_SMEM>>>(Sh, Sl, W5h, W5l, nullptr, nullptr, 128, 32, 32, NPU,
                                                       e_r2b, C, C);
    conv1x1_f2_kernel<<<dim3(4, 2, BATCH), 256>>>(C, pre_w, pre_b, Z, 128, 64);

    // ---- VQ (fused Q plane staging into S) ----
    vq_kernel<<<256, 128>>>(Z, cb, hist, ssep, Sh, Sl);

    // ---- decoder ----
    conv3x3_wmma<<<dim3(8, 2, BATCH), 256, DYN_SMEM>>>(Sh, Sl, W6h, W6l, d_b1, Bb, 64, 128, 64, NPU,
                                                       nullptr, nullptr, nullptr);
    stage_in_kernel<<<4096, 256>>>(Bb, Sh, Sl, NPU, 1);
    conv3x3_wmma<<<dim3(8, 1, BATCH), 256, DYN_SMEM>>>(Sh, Sl, W7h, W7l, nullptr, nullptr, 128, 32, 32, NPU,
                                                       d_r1b, Bb, Bb);
    stage_in_kernel<<<4096, 256>>>(Bb, Sh, Sl, NPU, 1);
    conv3x3_wmma<<<dim3(8, 1, BATCH), 256, DYN_SMEM>>>(Sh, Sl, W8h, W8l, nullptr, nullptr, 128, 32, 32, NPU,
                                                       d_r2b, Bb, Bb);

    stage_in_kernel<<<4096, 256>>>(Bb, Sh, Sl, NPU, 1);
    convt_wmma<<<dim3(8, 4, BATCH), 256, DYN_SMEM>>>(Sh, Sl, W9h, W9l, dt_b1, A, NPU);

    convt4s2_kernel<<<dim3(64, 1, BATCH), 256>>>(A, dt_w2, dt_b2, out + 1, 64, 64, 64, 3, 0, 0);

    finalize_kernel<<<1, 512>>>(hist, ssep, out, out_size - 1);
}